// round 7
// baseline (speedup 1.0000x reference)
#include <cuda_runtime.h>
#include <cuda_bf16.h>

#define Bb 8
#define Nn 128
#define Gg 100
#define Tt 24
#define ITERS 40
#define LRc 2e-4f
#define TWO_RHO 20.0f
#define VOLLc 1000.0f
#define VOSPc 50.0f
#define NCHUNK 4
#define NPC (Nn/NCHUNK)

#define TG   (Tt*Gg)
#define BTG  (Bb*Tt*Gg)
#define BNT  (Bb*Nn*Tt)
#define BNTG (Bb*Nn*Tt*Gg)
#define BN   (Bb*Nn)
#define BT   (Bb*Tt)

// ---------------- device scratch ----------------
__device__ float d_dup[BNTG], d_ddn[BNTG];
__device__ float d_LS[BNT], d_SP[BNT];
__device__ float d_P[BTG], d_Rup[BTG], d_Rdn[BTG];
__device__ float d_dumax[BTG], d_ddmax[BTG], d_dumin[BTG], d_ddmin[BTG];
__device__ float d_U7[BTG], d_U8[BTG];
__device__ float d_LSmax[BT], d_SPmax[BT], d_LSmin[BT], d_SPmin[BT];
__device__ float d_gamma[Bb], d_WA[Bb], d_WB[Bb], d_SA[Bb], d_SB[Bb];
__device__ float d_Qmax[Bb], d_Qmin[Bb];
__device__ float d_Qn[BN], d_wq[BN], d_dmax[BN], d_dmin[BN];

// ---------------- init ----------------
__global__ __launch_bounds__(256) void init_zero() {
    int stride = gridDim.x * blockDim.x;
    for (int i = blockIdx.x * blockDim.x + threadIdx.x; i < BNTG; i += stride) {
        d_dup[i] = 0.f; d_ddn[i] = 0.f;
        if (i < BNT) { d_LS[i] = 0.f; d_SP[i] = 0.f; }
        if (i < BTG) {
            d_Rup[i] = 0.f; d_Rdn[i] = 0.f;
            d_dumax[i] = 0.f; d_ddmax[i] = 0.f;
            d_dumin[i] = 0.f; d_ddmin[i] = 0.f;
            d_U7[i] = 0.f; d_U8[i] = 0.f;
        }
        if (i < BT) { d_LSmax[i]=0.f; d_SPmax[i]=0.f; d_LSmin[i]=0.f; d_SPmin[i]=0.f; }
        if (i < BN) d_Qn[i] = 0.f;
        if (i < Bb) d_gamma[i] = 0.f;
    }
}

__global__ __launch_bounds__(256) void init_small(
    const float* __restrict__ omega, const float* __restrict__ om_min_,
    const float* __restrict__ om_max_, const float* __restrict__ pmin_,
    const float* __restrict__ pmax_)
{
    int b = blockIdx.x, tid = threadIdx.x;
    for (int i = tid; i < TG; i += 256) {
        int g = i % Gg;
        d_P[b*TG + i] = 0.5f * (pmin_[g] + pmax_[g]);
    }
    float dm = 0.f, dn = 0.f;
    if (tid < Nn) {
        for (int t = 0; t < Tt; t++) {
            float om = omega[(b*Nn + tid)*Tt + t];
            dm += om_max_[b*Tt + t] - om;
            dn += om - om_min_[b*Tt + t];
        }
        d_dmax[b*Nn + tid] = dm;
        d_dmin[b*Nn + tid] = dn;
        d_wq[b*Nn + tid] = 0.5f / (float)Nn;   // exact balanced-tie weight at v0
    }
    __shared__ float red[16];
    int w = tid >> 5, l = tid & 31;
    float s = dm, s2 = dn;
    for (int o = 16; o; o >>= 1) {
        s  += __shfl_down_sync(0xffffffffu, s,  o);
        s2 += __shfl_down_sync(0xffffffffu, s2, o);
    }
    if (l == 0) { red[w] = s; red[8 + w] = s2; }
    __syncthreads();
    if (tid == 0) {
        float a = 0.f, c = 0.f;
        for (int i = 0; i < 8; i++) { a += red[i]; c += red[8+i]; }
        d_SA[b] = 0.25f * a / (float)Nn;
        d_SB[b] = 0.25f * c / (float)Nn;
        d_WA[b] = 0.25f; d_WB[b] = 0.25f;
    }
}

// ---------------- big per-scenario update ----------------
// grid = B*T*NCHUNK (768), 128 threads (g). Updates d_up/d_dn/LS/SP,
// accumulates Qn (new state) and U7/U8 (old state).
__global__ __launch_bounds__(128) void big_step(
    const float* __restrict__ omega, const float* __restrict__ bG)
{
    int blk = blockIdx.x;
    int nc = blk & (NCHUNK - 1);
    int t  = (blk / NCHUNK) % Tt;
    int b  = blk / (NCHUNK * Tt);
    int tid = threadIdx.x, g = tid;
    bool act = (g < Gg);
    int n0 = nc * NPC;

    __shared__ float shLS[NPC], shSP[NPC], shOM[NPC], shWQ[NPC];
    __shared__ float shpart[2][4];

    if (tid < NPC) {
        int n = n0 + tid;
        shLS[tid] = d_LS[(b*Nn + n)*Tt + t];
        shSP[tid] = d_SP[(b*Nn + n)*Tt + t];
        shOM[tid] = omega[(b*Nn + n)*Tt + t];
        shWQ[tid] = d_wq[b*Nn + n];
    }
    float rtu = 0.f, rtd = 0.f, Ru = 0.f, Rd = 0.f;
    if (act) {
        float bg = bG[g];
        rtu = 2.0f * bg; rtd = 0.5f * bg;
        Ru = d_Rup[(b*Tt + t)*Gg + g];
        Rd = d_Rdn[(b*Tt + t)*Gg + g];
    }
    __syncthreads();

    int base0 = ((b*Nn + n0)*Tt + t)*Gg;
    int stride = Tt * Gg;
    int w = tid >> 5, l = tid & 31;
    float u7 = 0.f, u8 = 0.f;
    float du = 0.f, dd = 0.f;
    if (act) { du = d_dup[base0 + g]; dd = d_ddn[base0 + g]; }

    for (int ni = 0; ni < NPC; ++ni) {
        int base = base0 + ni * stride;
        float dun = 0.f, ddnx = 0.f;
        if (act && ni + 1 < NPC) {            // prefetch next scenario
            dun  = d_dup[base + stride + g];
            ddnx = d_ddn[base + stride + g];
        }
        float s = du - dd;
        for (int o = 16; o; o >>= 1) s += __shfl_down_sync(0xffffffffu, s, o);
        if (l == 0) shpart[ni & 1][w] = s;
        __syncthreads();
        float r2 = shpart[ni&1][0] + shpart[ni&1][1] + shpart[ni&1][2] + shpart[ni&1][3]
                 + shLS[ni] - shSP[ni] - shOM[ni];
        float wqn = shWQ[ni];
        float lsn = fmaxf(shLS[ni] - LRc * (wqn * VOLLc + TWO_RHO * r2), 0.f);
        float spn = fmaxf(shSP[ni] - LRc * (wqn * VOSPc - TWO_RHO * r2), 0.f);
        float q = 0.f;
        if (tid == 0) {
            int n = n0 + ni;
            d_LS[(b*Nn + n)*Tt + t] = lsn;
            d_SP[(b*Nn + n)*Tt + t] = spn;
            q = VOLLc * lsn + VOSPc * spn;
        }
        if (act) {
            float rl7 = fmaxf(du - Ru, 0.f);
            float rl8 = fmaxf(dd - Rd, 0.f);
            u7 += rl7; u8 += rl8;
            float ndu = fmaxf(du - LRc * (wqn * rtu + TWO_RHO * (r2 + rl7)), 0.f);
            float ndd = fmaxf(dd - LRc * (wqn * rtd + TWO_RHO * (rl8 - r2)), 0.f);
            d_dup[base + g] = ndu;
            d_ddn[base + g] = ndd;
            q += rtu * ndu + rtd * ndd;
        }
        for (int o = 16; o; o >>= 1) q += __shfl_down_sync(0xffffffffu, q, o);
        if (l == 0) atomicAdd(&d_Qn[b*Nn + n0 + ni], q);
        du = dun; dd = ddnx;
    }
    if (act) {
        atomicAdd(&d_U7[(b*Tt + t)*Gg + g], u7);
        atomicAdd(&d_U8[(b*Tt + t)*Gg + g], u8);
    }
}

// ---------------- small (first-stage) update ----------------
__global__ __launch_bounds__(256) void small_step(
    const float* __restrict__ fc, const float* __restrict__ omn,
    const float* __restrict__ omx, const float* __restrict__ eps_,
    const float* __restrict__ pmin_, const float* __restrict__ pmax_,
    const float* __restrict__ bG, int last)
{
    int b = blockIdx.x, tid = threadIdx.x;
    __shared__ float shP[TG];
    __shared__ float shr1[Tt], shr3[Tt], shr4[Tt];
    __shared__ float sred[32];
    __shared__ float shWA, shWB, shSA, shSB, shGam, shQmax, shQmin;

    if (tid == 0) { shWA = d_WA[b]; shWB = d_WB[b]; shSA = d_SA[b]; shSB = d_SB[b]; }
    for (int i = tid; i < TG; i += 256) shP[i] = d_P[b*TG + i];
    __syncthreads();

    int w = tid >> 5, l = tid & 31;
    // residuals r1[t], r3[t], r4[t]
    for (int t = w; t < Tt; t += 8) {
        float s1 = 0.f, s3 = 0.f, s4 = 0.f;
        for (int g = l; g < Gg; g += 32) {
            int idx = b*TG + t*Gg + g;
            s1 += shP[t*Gg + g];
            s3 += d_dumax[idx] - d_ddmax[idx];
            s4 += d_dumin[idx] - d_ddmin[idx];
        }
        for (int o = 16; o; o >>= 1) {
            s1 += __shfl_down_sync(0xffffffffu, s1, o);
            s3 += __shfl_down_sync(0xffffffffu, s3, o);
            s4 += __shfl_down_sync(0xffffffffu, s4, o);
        }
        if (l == 0) {
            shr1[t] = s1 - fc[b*Tt + t];
            shr3[t] = s3 + d_LSmax[b*Tt + t] - d_SPmax[b*Tt + t] - omx[b*Tt + t];
            shr4[t] = s4 + d_LSmin[b*Tt + t] - d_SPmin[b*Tt + t] - omn[b*Tt + t];
        }
    }
    __syncthreads();

    float WA = shWA, WB = shWB;
    float qmx = 0.f, qmn = 0.f;
    for (int i = tid; i < TG; i += 256) {
        int g = i % Gg, t = i / Gg;
        int idx = b*TG + i;
        float bg = bG[g], pmn = pmin_[g], pmx = pmax_[g];
        float rtu = 2.f * bg, rtd = 0.5f * bg;
        float P  = shP[i];
        float Ru = d_Rup[idx], Rd = d_Rdn[idx];
        float dux = d_dumax[idx], ddx = d_ddmax[idx];
        float dui = d_dumin[idx], ddi = d_ddmin[idx];
        float r5  = fmaxf(P + Ru - pmx, 0.f);
        float r6  = fmaxf(pmn - P + Rd, 0.f);
        float r9  = fmaxf(dux - Ru, 0.f), r10 = fmaxf(ddx - Rd, 0.f);
        float r11 = fmaxf(dui - Ru, 0.f), r12 = fmaxf(ddi - Rd, 0.f);
        float sl = 0.f, sr = 0.f;
        if (t > 0) {
            float dp = P - shP[i - Gg];
            float rl = fmaxf(fabsf(dp) - pmx, 0.f);
            sl = (dp > 0.f) ? rl : -rl;
        }
        if (t < Tt - 1) {
            float dp = shP[i + Gg] - P;
            float rl = fmaxf(fabsf(dp) - pmx, 0.f);
            sr = (dp > 0.f) ? rl : -rl;
        }
        float nP = P - LRc * (bg + TWO_RHO * (shr1[t] + r5 - r6 + sl - sr));
        nP = fminf(fmaxf(nP, pmn), pmx);
        float U7 = d_U7[idx], U8 = d_U8[idx];
        d_U7[idx] = 0.f; d_U8[idx] = 0.f;
        float nRu = fmaxf(Ru - LRc * (0.05f*bg + TWO_RHO * (r5 - U7 - r9 - r11)), 0.f);
        float nRd = fmaxf(Rd - LRc * (0.02f*bg + TWO_RHO * (r6 - U8 - r10 - r12)), 0.f);
        float ndux = fmaxf(dux - LRc * (WA*rtu + TWO_RHO * ( shr3[t] + r9 )), 0.f);
        float nddx = fmaxf(ddx - LRc * (WA*rtd + TWO_RHO * (-shr3[t] + r10)), 0.f);
        float ndui = fmaxf(dui - LRc * (WB*rtu + TWO_RHO * ( shr4[t] + r11)), 0.f);
        float nddi = fmaxf(ddi - LRc * (WB*rtd + TWO_RHO * (-shr4[t] + r12)), 0.f);
        d_P[idx] = nP; d_Rup[idx] = nRu; d_Rdn[idx] = nRd;
        d_dumax[idx] = ndux; d_ddmax[idx] = nddx;
        d_dumin[idx] = ndui; d_ddmin[idx] = nddi;
        qmx += rtu*ndux + rtd*nddx;
        qmn += rtu*ndui + rtd*nddi;
    }
    if (tid < Tt) {
        int t = tid, bt = b*Tt + t;
        float v;
        v = fmaxf(d_LSmax[bt] - LRc*(WA*VOLLc + TWO_RHO*shr3[t]), 0.f); d_LSmax[bt] = v; qmx += VOLLc*v;
        v = fmaxf(d_SPmax[bt] - LRc*(WA*VOSPc - TWO_RHO*shr3[t]), 0.f); d_SPmax[bt] = v; qmx += VOSPc*v;
        v = fmaxf(d_LSmin[bt] - LRc*(WB*VOLLc + TWO_RHO*shr4[t]), 0.f); d_LSmin[bt] = v; qmn += VOLLc*v;
        v = fmaxf(d_SPmin[bt] - LRc*(WB*VOSPc - TWO_RHO*shr4[t]), 0.f); d_SPmin[bt] = v; qmn += VOSPc*v;
    }
    // reduce qmx, qmn
    for (int o = 16; o; o >>= 1) {
        qmx += __shfl_down_sync(0xffffffffu, qmx, o);
        qmn += __shfl_down_sync(0xffffffffu, qmn, o);
    }
    if (l == 0) { sred[w] = qmx; sred[8 + w] = qmn; }
    __syncthreads();
    if (tid == 0) {
        float Qx = 0.f, Qm = 0.f;
        for (int i = 0; i < 8; i++) { Qx += sred[i]; Qm += sred[8+i]; }
        float gm = fmaxf(d_gamma[b] - LRc * (eps_[b] - shSA - shSB), 0.f);
        d_gamma[b] = gm; shGam = gm;
        d_Qmax[b] = Qx; d_Qmin[b] = Qm;
        shQmax = Qx; shQmin = Qm;
    }
    __syncthreads();

    // next-iteration phi weights (exact lax.max tie semantics)
    float wa = 0.f, wb = 0.f, sa = 0.f, sb = 0.f;
    if (tid < Nn) {
        float Qn  = d_Qn[b*Nn + tid];
        float dmx = d_dmax[b*Nn + tid], dmn = d_dmin[b*Nn + tid];
        float Ap = shQmax - shGam * dmx;
        float Bp = shQmin - shGam * dmn;
        float M  = fmaxf(Ap, Bp);
        float wq = (Qn > M) ? 1.f : ((Qn == M) ? 0.5f : 0.f);
        float aw = (Ap > Bp) ? 1.f : ((Ap == Bp) ? 0.5f : 0.f);
        float bw = (Bp > Ap) ? 1.f : ((Ap == Bp) ? 0.5f : 0.f);
        float wm = 1.f - wq;
        d_wq[b*Nn + tid] = wq * (1.f / (float)Nn);
        if (!last) d_Qn[b*Nn + tid] = 0.f;
        wa = wm * aw; wb = wm * bw;
        sa = wa * dmx; sb = wb * dmn;
    }
    __syncthreads();
    for (int o = 16; o; o >>= 1) {
        wa += __shfl_down_sync(0xffffffffu, wa, o);
        wb += __shfl_down_sync(0xffffffffu, wb, o);
        sa += __shfl_down_sync(0xffffffffu, sa, o);
        sb += __shfl_down_sync(0xffffffffu, sb, o);
    }
    if (l == 0) { sred[w] = wa; sred[8+w] = wb; sred[16+w] = sa; sred[24+w] = sb; }
    __syncthreads();
    if (tid == 0) {
        float A=0,B=0,C=0,D=0;
        for (int i = 0; i < 8; i++) { A+=sred[i]; B+=sred[8+i]; C+=sred[16+i]; D+=sred[24+i]; }
        float inv = 1.f / (float)Nn;
        d_WA[b] = A*inv; d_WB[b] = B*inv; d_SA[b] = C*inv; d_SB[b] = D*inv;
    }
}

// ---------------- finalize: objective + outputs ----------------
__global__ __launch_bounds__(256) void finalize(
    const float* __restrict__ bG, const float* __restrict__ cG,
    const float* __restrict__ eps_, float* __restrict__ out)
{
    int b = blockIdx.x, tid = threadIdx.x;
    __shared__ float sred[16];
    float s1 = 0.f;
    for (int i = tid; i < TG; i += 256) {
        int g = i % Gg, t = i / Gg;
        float P = d_P[b*TG + i], Ru = d_Rup[b*TG + i], Rd = d_Rdn[b*TG + i];
        float bg = bG[g];
        float C = bg * P + cG[g];
        int oi = b*TG + g*Tt + t;            // [b][g][t] output layout
        out[oi] = P;
        out[BTG   + oi] = Ru;
        out[2*BTG + oi] = Rd;
        out[3*BTG + oi] = C;
        s1 += C + 0.05f*bg*Ru + 0.02f*bg*Rd;
    }
    float ph = 0.f;
    if (tid < Nn) {
        float Qn = d_Qn[b*Nn + tid];
        float gm = d_gamma[b];
        float Ap = d_Qmax[b] - gm * d_dmax[b*Nn + tid];
        float Bp = d_Qmin[b] - gm * d_dmin[b*Nn + tid];
        float phi = fmaxf(Qn, fmaxf(Ap, Bp));
        out[4*BTG + b*Nn + tid] = phi;
        ph = phi;
    }
    int w = tid >> 5, l = tid & 31;
    for (int o = 16; o; o >>= 1) {
        s1 += __shfl_down_sync(0xffffffffu, s1, o);
        ph += __shfl_down_sync(0xffffffffu, ph, o);
    }
    if (l == 0) { sred[w] = s1; sred[8+w] = ph; }
    __syncthreads();
    if (tid == 0) {
        float S = 0.f, PH = 0.f;
        for (int i = 0; i < 8; i++) { S += sred[i]; PH += sred[8+i]; }
        float gm = d_gamma[b];
        out[4*BTG + BN + b]      = gm;
        out[4*BTG + BN + Bb + b] = S + PH / (float)Nn + eps_[b] * gm;
    }
}

extern "C" void kernel_launch(void* const* d_in, const int* in_sizes, int n_in,
                              void* d_out, int out_size) {
    const float* forecast = (const float*)d_in[0];  // [B,T]
    const float* omega    = (const float*)d_in[1];  // [B,N,T]
    const float* om_min   = (const float*)d_in[2];  // [B,T]
    const float* om_max   = (const float*)d_in[3];  // [B,T]
    const float* eps      = (const float*)d_in[4];  // [B]
    const float* pmin     = (const float*)d_in[5];  // [G]
    const float* pmax     = (const float*)d_in[6];  // [G]
    const float* bG       = (const float*)d_in[7];  // [G]
    const float* cG       = (const float*)d_in[8];  // [G]
    float* out = (float*)d_out;
    (void)in_sizes; (void)n_in; (void)out_size;

    init_zero<<<2400, 256>>>();
    init_small<<<Bb, 256>>>(omega, om_min, om_max, pmin, pmax);
    for (int it = 0; it < ITERS; ++it) {
        big_step<<<Bb*Tt*NCHUNK, 128>>>(omega, bG);
        small_step<<<Bb, 256>>>(forecast, om_min, om_max, eps, pmin, pmax, bG,
                                (it == ITERS - 1) ? 1 : 0);
    }
    finalize<<<Bb, 256>>>(bG, cG, eps, out);
}

// round 8
// speedup vs baseline: 1.5011x; 1.5011x over previous
#include <cuda_runtime.h>
#include <cuda_bf16.h>

#define Bb 8
#define Nn 128
#define Gg 100
#define Tt 24
#define ITERS 40
#define LRc 2e-4f
#define TWO_RHO 20.0f
#define VOLLc 1000.0f
#define VOSPc 50.0f
#define NCHUNK 8
#define NPC (Nn/NCHUNK)      // 16

#define TG   (Tt*Gg)         // 2400
#define BTG  (Bb*TG)         // 19200
#define BNT  (Bb*Nn*Tt)      // 24576
#define BNTG (Bb*Nn*Tt*Gg)   // 2457600
#define BN   (Bb*Nn)         // 1024
#define BT   (Bb*Tt)         // 192

// ---------------- device scratch ----------------
__device__ float d_dup[BNTG], d_ddn[BNTG];
__device__ float d_LS[BNT], d_SP[BNT];
__device__ float d_Pbuf[2][BTG];
__device__ float d_Rup[BTG], d_Rdn[BTG];
__device__ float d_dumax[BTG], d_ddmax[BTG], d_dumin[BTG], d_ddmin[BTG];
__device__ float d_U7P[NCHUNK*BTG], d_U8P[NCHUNK*BTG];
__device__ float d_LSmax[BT], d_SPmax[BT], d_LSmin[BT], d_SPmin[BT];
__device__ float d_QmaxP[BT], d_QminP[BT];
__device__ float d_gam[2][Bb];
__device__ float d_WA[Bb], d_WB[Bb];
__device__ float d_QnBuf[2][BN];
__device__ float d_dmax[BN], d_dmin[BN];

__device__ __forceinline__ float wsum(float v) {
    #pragma unroll
    for (int o = 16; o; o >>= 1) v += __shfl_down_sync(0xffffffffu, v, o);
    return v;
}

// ---------------- init ----------------
__global__ __launch_bounds__(256) void init_zero() {
    int stride = gridDim.x * blockDim.x;
    for (int i = blockIdx.x * blockDim.x + threadIdx.x; i < BNTG; i += stride) {
        d_dup[i] = 0.f; d_ddn[i] = 0.f;
        if (i < BNT) { d_LS[i] = 0.f; d_SP[i] = 0.f; }
        if (i < BTG) {
            d_Rup[i] = 0.f; d_Rdn[i] = 0.f;
            d_dumax[i] = 0.f; d_ddmax[i] = 0.f;
            d_dumin[i] = 0.f; d_ddmin[i] = 0.f;
        }
        if (i < BT) { d_LSmax[i]=0.f; d_SPmax[i]=0.f; d_LSmin[i]=0.f; d_SPmin[i]=0.f; }
        if (i < BN) { d_QnBuf[0][i] = 0.f; d_QnBuf[1][i] = 0.f; }
        if (i < Bb) { d_gam[0][i] = 0.f; d_gam[1][i] = 0.f; }
    }
}

__global__ __launch_bounds__(256) void init_small(
    const float* __restrict__ omega, const float* __restrict__ om_min_,
    const float* __restrict__ om_max_, const float* __restrict__ pmin_,
    const float* __restrict__ pmax_)
{
    int b = blockIdx.x, tid = threadIdx.x;
    for (int i = tid; i < TG; i += 256) {
        int g = i % Gg;
        d_Pbuf[0][b*TG + i] = 0.5f * (pmin_[g] + pmax_[g]);
    }
    if (tid < Nn) {
        float dm = 0.f, dn = 0.f;
        for (int t = 0; t < Tt; t++) {
            float om = omega[(b*Nn + tid)*Tt + t];
            dm += om_max_[b*Tt + t] - om;
            dn += om - om_min_[b*Tt + t];
        }
        d_dmax[b*Nn + tid] = dm;
        d_dmin[b*Nn + tid] = dn;
    }
}

// ---------------- big per-scenario update (with weight/gamma prologue) ----
// grid = B*T*NCHUNK (1536), 128 threads (g / n).
__global__ __launch_bounds__(128) void big_step(
    const float* __restrict__ omega, const float* __restrict__ bG,
    const float* __restrict__ eps_, int it)
{
    int blk = blockIdx.x;
    int nc = blk % NCHUNK;
    int t  = (blk / NCHUNK) % Tt;
    int b  = blk / (NCHUNK * Tt);
    int tid = threadIdx.x, g = tid;
    bool act = (g < Gg);
    int n0 = nc * NPC;
    int p = it & 1;
    int w = tid >> 5, l = tid & 31;

    __shared__ float shWQ[NPC];
    __shared__ float shLS[NPC], shSP[NPC], shOM[NPC];
    __shared__ float shpart[2][4];
    __shared__ float sred[16];

    // ---- prologue: phi branch weights (exact lax.max tie semantics) + gamma ----
    {
        float gamma_old = d_gam[p][b];
        float dmx = d_dmax[b*Nn + tid];
        float dmn = d_dmin[b*Nn + tid];
        float wq, wa, wb;
        if (it == 0) { wq = 0.5f; wa = 0.25f; wb = 0.25f; }
        else {
            float Qmax = 0.f, Qmin = 0.f;
            #pragma unroll
            for (int tt = 0; tt < Tt; ++tt) {
                Qmax += d_QmaxP[b*Tt + tt];
                Qmin += d_QminP[b*Tt + tt];
            }
            float Qn = d_QnBuf[p ^ 1][b*Nn + tid];
            float Ap = Qmax - gamma_old * dmx;
            float Bp = Qmin - gamma_old * dmn;
            float M = fmaxf(Ap, Bp);
            wq = (Qn > M) ? 1.f : ((Qn == M) ? 0.5f : 0.f);
            float aw = (Ap > Bp) ? 1.f : ((Ap == Bp) ? 0.5f : 0.f);
            float bw = (Bp > Ap) ? 1.f : ((Ap == Bp) ? 0.5f : 0.f);
            float wm = 1.f - wq;
            wa = wm * aw; wb = wm * bw;
        }
        if (tid >= n0 && tid < n0 + NPC)
            shWQ[tid - n0] = wq * (1.f / (float)Nn);
        float v0 = wsum(wa), v1 = wsum(wb), v2 = wsum(wa * dmx), v3 = wsum(wb * dmn);
        if (l == 0) { sred[w] = v0; sred[4+w] = v1; sred[8+w] = v2; sred[12+w] = v3; }
        if (tid < NPC) {
            int n = n0 + tid;
            shLS[tid] = d_LS[(b*Nn + n)*Tt + t];
            shSP[tid] = d_SP[(b*Nn + n)*Tt + t];
            shOM[tid] = omega[(b*Nn + n)*Tt + t];
        }
        __syncthreads();
        if (tid == 0) {
            float inv = 1.f / (float)Nn;
            float A = (sred[0]+sred[1]+sred[2]+sred[3]) * inv;
            float B = (sred[4]+sred[5]+sred[6]+sred[7]) * inv;
            float C = (sred[8]+sred[9]+sred[10]+sred[11]) * inv;
            float D = (sred[12]+sred[13]+sred[14]+sred[15]) * inv;
            d_WA[b] = A; d_WB[b] = B;          // identical in every block: benign
            d_gam[p^1][b] = fmaxf(gamma_old - LRc * (eps_[b] - C - D), 0.f);
        }
    }

    // ---- main scenario loop ----
    float rtu = 0.f, rtd = 0.f, Ru = 0.f, Rd = 0.f;
    if (act) {
        float bg = bG[g];
        rtu = 2.0f * bg; rtd = 0.5f * bg;
        Ru = d_Rup[(b*Tt + t)*Gg + g];
        Rd = d_Rdn[(b*Tt + t)*Gg + g];
    }
    int base0 = ((b*Nn + n0)*Tt + t)*Gg;
    int stride = Tt * Gg;
    float u7 = 0.f, u8 = 0.f;
    float du = 0.f, dd = 0.f;
    if (act) { du = d_dup[base0 + g]; dd = d_ddn[base0 + g]; }

    for (int ni = 0; ni < NPC; ++ni) {
        int base = base0 + ni * stride;
        float dun = 0.f, ddnx = 0.f;
        if (act && ni + 1 < NPC) {             // prefetch next scenario
            dun  = d_dup[base + stride + g];
            ddnx = d_ddn[base + stride + g];
        }
        float s = wsum(du - dd);
        if (l == 0) shpart[ni & 1][w] = s;
        __syncthreads();
        float r2 = shpart[ni&1][0] + shpart[ni&1][1] + shpart[ni&1][2] + shpart[ni&1][3]
                 + shLS[ni] - shSP[ni] - shOM[ni];
        float wqn = shWQ[ni];
        float q = 0.f;
        if (tid == 0) {
            int n = n0 + ni;
            float lsn = fmaxf(shLS[ni] - LRc * (wqn * VOLLc + TWO_RHO * r2), 0.f);
            float spn = fmaxf(shSP[ni] - LRc * (wqn * VOSPc - TWO_RHO * r2), 0.f);
            d_LS[(b*Nn + n)*Tt + t] = lsn;
            d_SP[(b*Nn + n)*Tt + t] = spn;
            q = VOLLc * lsn + VOSPc * spn;
        }
        if (act) {
            float rl7 = fmaxf(du - Ru, 0.f);
            float rl8 = fmaxf(dd - Rd, 0.f);
            u7 += rl7; u8 += rl8;
            float ndu = fmaxf(du - LRc * (wqn * rtu + TWO_RHO * (r2 + rl7)), 0.f);
            float ndd = fmaxf(dd - LRc * (wqn * rtd + TWO_RHO * (rl8 - r2)), 0.f);
            d_dup[base + g] = ndu;
            d_ddn[base + g] = ndd;
            q += rtu * ndu + rtd * ndd;
        }
        q = wsum(q);
        if (l == 0) atomicAdd(&d_QnBuf[p][b*Nn + n0 + ni], q);
        du = dun; dd = ddnx;
    }
    if (act) {
        int u = ((b*Tt + t)*NCHUNK + nc)*Gg + g;
        d_U7P[u] = u7; d_U8P[u] = u8;          // plain stores, no atomics
    }
}

// ---------------- first-stage update, one block per (b,t) ----------------
__global__ __launch_bounds__(128) void small_step(
    const float* __restrict__ fc, const float* __restrict__ omn,
    const float* __restrict__ omx, const float* __restrict__ pmin_,
    const float* __restrict__ pmax_, const float* __restrict__ bG, int it)
{
    int blk = blockIdx.x;
    int b = blk / Tt, t = blk % Tt;
    int bt = b*Tt + t;
    int tid = threadIdx.x, g = tid;
    bool act = (g < Gg);
    int idx = bt*Gg + g;
    int pr = it & 1, pw = pr ^ 1;
    int w = tid >> 5, l = tid & 31;
    __shared__ float sred[12];
    __shared__ float shc[5];

    float P=0,Pm=0,Pp=0,Ru=0,Rd=0,dux=0,ddx=0,dui=0,ddi=0,U7=0,U8=0,bg=0,pmn=0,pmx=0;
    if (act) {
        P = d_Pbuf[pr][idx];
        if (t > 0)      Pm = d_Pbuf[pr][idx - Gg];
        if (t < Tt - 1) Pp = d_Pbuf[pr][idx + Gg];
        Ru = d_Rup[idx]; Rd = d_Rdn[idx];
        dux = d_dumax[idx]; ddx = d_ddmax[idx];
        dui = d_dumin[idx]; ddi = d_ddmin[idx];
        #pragma unroll
        for (int nc = 0; nc < NCHUNK; ++nc) {
            U7 += d_U7P[(bt*NCHUNK + nc)*Gg + g];
            U8 += d_U8P[(bt*NCHUNK + nc)*Gg + g];
        }
        bg = bG[g]; pmn = pmin_[g]; pmx = pmax_[g];
    }
    float s1 = wsum(P), s3 = wsum(dux - ddx), s4 = wsum(dui - ddi);
    if (l == 0) { sred[w] = s1; sred[4+w] = s3; sred[8+w] = s4; }
    __syncthreads();
    if (tid == 0) {
        shc[0] = sred[0]+sred[1]+sred[2]+sred[3] - fc[bt];
        shc[1] = sred[4]+sred[5]+sred[6]+sred[7] + d_LSmax[bt] - d_SPmax[bt] - omx[bt];
        shc[2] = sred[8]+sred[9]+sred[10]+sred[11] + d_LSmin[bt] - d_SPmin[bt] - omn[bt];
        shc[3] = d_WA[b]; shc[4] = d_WB[b];
    }
    __syncthreads();
    float r1 = shc[0], r3 = shc[1], r4 = shc[2], WA = shc[3], WB = shc[4];
    float qmx = 0.f, qmn = 0.f;
    if (act) {
        float rtu = 2.f*bg, rtd = 0.5f*bg;
        float r5  = fmaxf(P + Ru - pmx, 0.f);
        float r6  = fmaxf(pmn - P + Rd, 0.f);
        float r9  = fmaxf(dux - Ru, 0.f), r10 = fmaxf(ddx - Rd, 0.f);
        float r11 = fmaxf(dui - Ru, 0.f), r12 = fmaxf(ddi - Rd, 0.f);
        float sl = 0.f, sr = 0.f;
        if (t > 0)      { float dp = P - Pm; float rl = fmaxf(fabsf(dp) - pmx, 0.f); sl = (dp > 0.f) ? rl : -rl; }
        if (t < Tt - 1) { float dp = Pp - P; float rl = fmaxf(fabsf(dp) - pmx, 0.f); sr = (dp > 0.f) ? rl : -rl; }
        float nP = P - LRc * (bg + TWO_RHO * (r1 + r5 - r6 + sl - sr));
        nP = fminf(fmaxf(nP, pmn), pmx);
        float nRu = fmaxf(Ru - LRc * (0.05f*bg + TWO_RHO * (r5 - U7 - r9 - r11)), 0.f);
        float nRd = fmaxf(Rd - LRc * (0.02f*bg + TWO_RHO * (r6 - U8 - r10 - r12)), 0.f);
        float ndux = fmaxf(dux - LRc * (WA*rtu + TWO_RHO * ( r3 + r9 )), 0.f);
        float nddx = fmaxf(ddx - LRc * (WA*rtd + TWO_RHO * (-r3 + r10)), 0.f);
        float ndui = fmaxf(dui - LRc * (WB*rtu + TWO_RHO * ( r4 + r11)), 0.f);
        float nddi = fmaxf(ddi - LRc * (WB*rtd + TWO_RHO * (-r4 + r12)), 0.f);
        d_Pbuf[pw][idx] = nP; d_Rup[idx] = nRu; d_Rdn[idx] = nRd;
        d_dumax[idx] = ndux; d_ddmax[idx] = nddx;
        d_dumin[idx] = ndui; d_ddmin[idx] = nddi;
        qmx = rtu*ndux + rtd*nddx;
        qmn = rtu*ndui + rtd*nddi;
    }
    if (tid == 0) {
        float v;
        v = fmaxf(d_LSmax[bt] - LRc*(WA*VOLLc + TWO_RHO*r3), 0.f); d_LSmax[bt] = v; qmx += VOLLc*v;
        v = fmaxf(d_SPmax[bt] - LRc*(WA*VOSPc - TWO_RHO*r3), 0.f); d_SPmax[bt] = v; qmx += VOSPc*v;
        v = fmaxf(d_LSmin[bt] - LRc*(WB*VOLLc + TWO_RHO*r4), 0.f); d_LSmin[bt] = v; qmn += VOLLc*v;
        v = fmaxf(d_SPmin[bt] - LRc*(WB*VOSPc - TWO_RHO*r4), 0.f); d_SPmin[bt] = v; qmn += VOSPc*v;
    }
    qmx = wsum(qmx); qmn = wsum(qmn);
    if (l == 0) { sred[w] = qmx; sred[4+w] = qmn; }
    __syncthreads();
    if (tid == 0) {
        d_QmaxP[bt] = sred[0]+sred[1]+sred[2]+sred[3];
        d_QminP[bt] = sred[4]+sred[5]+sred[6]+sred[7];
    }
    if (t == 0) d_QnBuf[pw][b*Nn + tid] = 0.f;   // ready for next iter's accumulation
}

// ---------------- finalize: objective + outputs ----------------
__global__ __launch_bounds__(256) void finalize(
    const float* __restrict__ bG, const float* __restrict__ cG,
    const float* __restrict__ eps_, float* __restrict__ out)
{
    int b = blockIdx.x, tid = threadIdx.x;
    __shared__ float sred[16];
    float s1 = 0.f;
    for (int i = tid; i < TG; i += 256) {
        int g = i % Gg, t = i / Gg;
        float P = d_Pbuf[0][b*TG + i], Ru = d_Rup[b*TG + i], Rd = d_Rdn[b*TG + i];
        float bg = bG[g];
        float C = bg * P + cG[g];
        int oi = b*TG + g*Tt + t;            // [b][g][t] output layout
        out[oi] = P;
        out[BTG   + oi] = Ru;
        out[2*BTG + oi] = Rd;
        out[3*BTG + oi] = C;
        s1 += C + 0.05f*bg*Ru + 0.02f*bg*Rd;
    }
    float Qmax = 0.f, Qmin = 0.f;
    #pragma unroll
    for (int tt = 0; tt < Tt; ++tt) { Qmax += d_QmaxP[b*Tt + tt]; Qmin += d_QminP[b*Tt + tt]; }
    float gm = d_gam[0][b];                  // gamma after 40 updates
    float ph = 0.f;
    if (tid < Nn) {
        float Qn = d_QnBuf[1][b*Nn + tid];   // Qn of final state
        float Ap = Qmax - gm * d_dmax[b*Nn + tid];
        float Bp = Qmin - gm * d_dmin[b*Nn + tid];
        float phi = fmaxf(Qn, fmaxf(Ap, Bp));
        out[4*BTG + b*Nn + tid] = phi;
        ph = phi;
    }
    int w = tid >> 5, l = tid & 31;
    s1 = wsum(s1); ph = wsum(ph);
    if (l == 0) { sred[w] = s1; sred[8+w] = ph; }
    __syncthreads();
    if (tid == 0) {
        float S = 0.f, PH = 0.f;
        for (int i = 0; i < 8; i++) { S += sred[i]; PH += sred[8+i]; }
        out[4*BTG + BN + b]      = gm;
        out[4*BTG + BN + Bb + b] = S + PH / (float)Nn + eps_[b] * gm;
    }
}

extern "C" void kernel_launch(void* const* d_in, const int* in_sizes, int n_in,
                              void* d_out, int out_size) {
    const float* forecast = (const float*)d_in[0];  // [B,T]
    const float* omega    = (const float*)d_in[1];  // [B,N,T]
    const float* om_min   = (const float*)d_in[2];  // [B,T]
    const float* om_max   = (const float*)d_in[3];  // [B,T]
    const float* eps      = (const float*)d_in[4];  // [B]
    const float* pmin     = (const float*)d_in[5];  // [G]
    const float* pmax     = (const float*)d_in[6];  // [G]
    const float* bG       = (const float*)d_in[7];  // [G]
    const float* cG       = (const float*)d_in[8];  // [G]
    float* out = (float*)d_out;
    (void)in_sizes; (void)n_in; (void)out_size;

    init_zero<<<2400, 256>>>();
    init_small<<<Bb, 256>>>(omega, om_min, om_max, pmin, pmax);
    for (int it = 0; it < ITERS; ++it) {
        big_step<<<Bb*Tt*NCHUNK, 128>>>(omega, bG, eps, it);
        small_step<<<BT, 128>>>(forecast, om_min, om_max, pmin, pmax, bG, it);
    }
    finalize<<<Bb, 256>>>(bG, cG, eps, out);
}

// round 11
// speedup vs baseline: 1.9701x; 1.3125x over previous
#include <cuda_runtime.h>
#include <cuda_bf16.h>

#define Bb 8
#define Nn 128
#define Gg 100
#define Tt 24
#define ITERS 40
#define LRc 2e-4f
#define TWO_RHO 20.0f
#define VOLLc 1000.0f
#define VOSPc 50.0f

#define NCHB 2              // big blocks per (b,t)
#define NWRP 8              // warps per block
#define SPW  8              // scenarios per warp  (2*8*8 = 128 = Nn)

#define TG   (Tt*Gg)        // 2400
#define BTG  (Bb*TG)        // 19200
#define BNTG (Bb*Nn*Tt*Gg)
#define BN   (Bb*Nn)        // 1024
#define BT   (Bb*Tt)        // 192
#define GRID (BT*NCHB)      // 384

// ---------------- device state ----------------
__device__ float d_dup[BNTG], d_ddn[BNTG];
__device__ float d_LS[BT*Nn], d_SP[BT*Nn];          // [b][t][n]
__device__ float d_Pbuf[2][BTG];
__device__ float d_Rup[BTG], d_Rdn[BTG];
__device__ float d_dumax[BTG], d_ddmax[BTG], d_dumin[BTG], d_ddmin[BTG];
__device__ float d_U7P[BT*NCHB*Gg], d_U8P[BT*NCHB*Gg];
__device__ float d_LSmax[BT], d_SPmax[BT], d_LSmin[BT], d_SPmin[BT];
__device__ float d_QmaxP[BT], d_QminP[BT];
__device__ float d_QnP[BT*Nn];                      // [b][t][n]
__device__ float d_gam[2][Bb];
__device__ float d_WA[Bb], d_WB[Bb];
__device__ float d_dmax[BN], d_dmin[BN];

// ---------------- grid barrier (single-wave) ----------------
__device__ unsigned g_cnt = 0;
__device__ volatile unsigned g_gen = 0;

__device__ __forceinline__ void grid_barrier() {
    __syncthreads();
    if (threadIdx.x == 0) {
        __threadfence();
        unsigned gen = g_gen;
        if (atomicAdd(&g_cnt, 1u) == (unsigned)(GRID - 1)) {
            g_cnt = 0;
            __threadfence();
            g_gen = gen + 1u;
        } else {
            while (g_gen == gen) __nanosleep(32);
        }
        __threadfence();
    }
    __syncthreads();
}

__device__ __forceinline__ float wsum(float v) {
    #pragma unroll
    for (int o = 16; o; o >>= 1) v += __shfl_down_sync(0xffffffffu, v, o);
    return v;
}
__device__ __forceinline__ float wsum_all(float v) {
    #pragma unroll
    for (int o = 16; o; o >>= 1) v += __shfl_xor_sync(0xffffffffu, v, o);
    return v;
}

// ---------------- the whole solver, one launch ----------------
__global__ __launch_bounds__(256, 3) void solver(
    const float* __restrict__ fc,   const float* __restrict__ omega,
    const float* __restrict__ omn,  const float* __restrict__ omx,
    const float* __restrict__ eps_, const float* __restrict__ pmin_,
    const float* __restrict__ pmax_,const float* __restrict__ bG,
    const float* __restrict__ cG,   float* __restrict__ out)
{
    int blk = blockIdx.x, tid = threadIdx.x;
    int w = tid >> 5, l = tid & 31;
    int nc = blk & (NCHB - 1);
    int bt = blk >> 1;               // b*Tt + t
    int t  = bt % Tt, b = bt / Tt;

    __shared__ float shLS[64], shSP[64], shOM[64], shWQ[64];
    __shared__ float shU7[NWRP*104], shU8[NWRP*104];
    __shared__ float sred[32];
    __shared__ float shQm[Tt], shQi[Tt];
    __shared__ float shc[8];

    // per-thread g constants (4 g's per lane in big phase)
    float bgv[4];
    #pragma unroll
    for (int j = 0; j < 4; ++j) {
        int g = l + 32*j;
        bgv[j] = (g < Gg) ? bG[g] : 0.f;
    }

    for (int it = 0; it < ITERS; ++it) {
        int p = it & 1;

        // ================= prologue: weights + gamma =================
        float dmx = 0.f, dmn = 0.f;
        if (tid < Nn) {
            if (it == 0) {
                #pragma unroll 4
                for (int tt = 0; tt < Tt; ++tt) {
                    float om = omega[(b*Nn + tid)*Tt + tt];
                    dmx += omx[b*Tt + tt] - om;
                    dmn += om - omn[b*Tt + tt];
                }
                d_dmax[b*Nn + tid] = dmx;
                d_dmin[b*Nn + tid] = dmn;
            } else {
                dmx = d_dmax[b*Nn + tid];
                dmn = d_dmin[b*Nn + tid];
            }
        }
        if (it > 0) {
            if (tid < Tt) shQm[tid] = __ldcg(&d_QmaxP[b*Tt + tid]);
            else if (tid >= 32 && tid < 32 + Tt) shQi[tid-32] = __ldcg(&d_QminP[b*Tt + tid - 32]);
        }
        __syncthreads();

        float gamma_old = (it == 0) ? 0.f : __ldcg(&d_gam[p][b]);
        float wa = 0.f, wb = 0.f;
        float wq = 0.f;
        if (tid < Nn) {
            if (it == 0) { wq = 0.5f; wa = 0.25f; wb = 0.25f; }
            else {
                float Qmax = 0.f, Qmin = 0.f;
                #pragma unroll 8
                for (int tt = 0; tt < Tt; ++tt) { Qmax += shQm[tt]; Qmin += shQi[tt]; }
                float Qn = 0.f;
                #pragma unroll 4
                for (int tt = 0; tt < Tt; ++tt)
                    Qn += __ldcg(&d_QnP[(b*Tt + tt)*Nn + tid]);
                float Ap = Qmax - gamma_old * dmx;
                float Bp = Qmin - gamma_old * dmn;
                float M  = fmaxf(Ap, Bp);
                wq = (Qn > M) ? 1.f : ((Qn == M) ? 0.5f : 0.f);
                float aw = (Ap > Bp) ? 1.f : ((Ap == Bp) ? 0.5f : 0.f);
                float bw = (Bp > Ap) ? 1.f : ((Ap == Bp) ? 0.5f : 0.f);
                float wm = 1.f - wq;
                wa = wm * aw; wb = wm * bw;
            }
            if (tid >= nc*64 && tid < nc*64 + 64)
                shWQ[tid - nc*64] = wq * (1.f / (float)Nn);
        }
        {
            float v0 = wsum(wa), v1 = wsum(wb), v2 = wsum(wa * dmx), v3 = wsum(wb * dmn);
            if (l == 0) { sred[w] = v0; sred[8+w] = v1; sred[16+w] = v2; sred[24+w] = v3; }
        }
        // stage this block's 64 scenarios' LS/SP/omega
        if (tid < 64) {
            int n = nc*64 + tid;
            shLS[tid] = (it > 0) ? d_LS[bt*Nn + n] : 0.f;
            shSP[tid] = (it > 0) ? d_SP[bt*Nn + n] : 0.f;
            shOM[tid] = omega[(b*Nn + n)*Tt + t];
        }
        __syncthreads();
        if (tid == 0) {
            float A=0,B=0,C=0,D=0;
            #pragma unroll
            for (int i = 0; i < 8; i++) { A+=sred[i]; B+=sred[8+i]; C+=sred[16+i]; D+=sred[24+i]; }
            float inv = 1.f / (float)Nn;
            __stcg(&d_WA[b], A*inv);
            __stcg(&d_WB[b], B*inv);
            __stcg(&d_gam[p^1][b], fmaxf(gamma_old - LRc * (eps_[b] - C*inv - D*inv), 0.f));
        }

        // ================= big phase: warp-per-scenario =================
        float Ru[4], Rd[4];
        #pragma unroll
        for (int j = 0; j < 4; ++j) {
            int g = l + 32*j;
            Ru[j] = (it > 0 && g < Gg) ? __ldcg(&d_Rup[bt*Gg + g]) : 0.f;
            Rd[j] = (it > 0 && g < Gg) ? __ldcg(&d_Rdn[bt*Gg + g]) : 0.f;
        }
        float u7a[4] = {0,0,0,0}, u8a[4] = {0,0,0,0};
        int nfirst = nc*64 + w*SPW;
        long base0 = ((long)(b*Nn + nfirst)*Tt + t)*Gg;
        const long nstride = (long)Tt*Gg;

        float du[4], dd[4];
        #pragma unroll
        for (int j = 0; j < 4; ++j) {
            int g = l + 32*j;
            du[j] = (it > 0 && g < Gg) ? d_dup[base0 + g] : 0.f;
            dd[j] = (it > 0 && g < Gg) ? d_ddn[base0 + g] : 0.f;
        }

        for (int s = 0; s < SPW; ++s) {
            long base = base0 + s*nstride;
            float du2[4], dd2[4];
            if (s + 1 < SPW) {
                #pragma unroll
                for (int j = 0; j < 4; ++j) {
                    int g = l + 32*j;
                    du2[j] = (it > 0 && g < Gg) ? d_dup[base + nstride + g] : 0.f;
                    dd2[j] = (it > 0 && g < Gg) ? d_ddn[base + nstride + g] : 0.f;
                }
            }
            int si = w*SPW + s;
            float r2p = (du[0]-dd[0]) + (du[1]-dd[1]) + (du[2]-dd[2]) + (du[3]-dd[3]);
            float r2 = wsum_all(r2p) + shLS[si] - shSP[si] - shOM[si];
            float wqn = shWQ[si];
            float q = 0.f;
            #pragma unroll
            for (int j = 0; j < 4; ++j) {
                int g = l + 32*j;
                if (g < Gg) {
                    float rtu = 2.0f * bgv[j], rtd = 0.5f * bgv[j];
                    float rl7 = fmaxf(du[j] - Ru[j], 0.f);
                    float rl8 = fmaxf(dd[j] - Rd[j], 0.f);
                    u7a[j] += rl7; u8a[j] += rl8;
                    float ndu = fmaxf(du[j] - LRc * (wqn * rtu + TWO_RHO * (r2 + rl7)), 0.f);
                    float ndd = fmaxf(dd[j] - LRc * (wqn * rtd + TWO_RHO * (rl8 - r2)), 0.f);
                    d_dup[base + g] = ndu;
                    d_ddn[base + g] = ndd;
                    q += rtu * ndu + rtd * ndd;
                }
            }
            q = wsum(q);
            if (l == 0) {
                int n = nfirst + s;
                float lsn = fmaxf(shLS[si] - LRc * (wqn * VOLLc + TWO_RHO * r2), 0.f);
                float spn = fmaxf(shSP[si] - LRc * (wqn * VOSPc - TWO_RHO * r2), 0.f);
                d_LS[bt*Nn + n] = lsn;
                d_SP[bt*Nn + n] = spn;
                __stcg(&d_QnP[bt*Nn + n], q + VOLLc * lsn + VOSPc * spn);
            }
            #pragma unroll
            for (int j = 0; j < 4; ++j) { du[j] = du2[j]; dd[j] = dd2[j]; }
        }
        #pragma unroll
        for (int j = 0; j < 4; ++j) {
            int g = l + 32*j;
            if (g < Gg) { shU7[w*104 + g] = u7a[j]; shU8[w*104 + g] = u8a[j]; }
        }
        __syncthreads();
        if (tid < Gg) {
            float s7 = 0.f, s8 = 0.f;
            #pragma unroll
            for (int ww = 0; ww < NWRP; ++ww) { s7 += shU7[ww*104 + tid]; s8 += shU8[ww*104 + tid]; }
            __stcg(&d_U7P[(bt*NCHB + nc)*Gg + tid], s7);
            __stcg(&d_U8P[(bt*NCHB + nc)*Gg + tid], s8);
        }

        grid_barrier();

        // ================= small phase: blocks 0..191, one (b,t) each ====
        if (blk < BT) {
            int bt2 = blk, b2 = blk / Tt, t2 = blk % Tt;
            int g = tid;
            bool act = (g < Gg);
            int idx = bt2*Gg + g;
            int pr = it & 1, pw = pr ^ 1;

            float P=0,Pm=0,Pp=0,Rux=0,Rdx=0,dux=0,ddx=0,dui=0,ddi=0,U7=0,U8=0,bg=0,pmn=0,pmx=0;
            if (act) {
                if (it == 0) {
                    float pv = 0.5f * (pmin_[g] + pmax_[g]);
                    P = pv; Pm = pv; Pp = pv;
                } else {
                    P = __ldcg(&d_Pbuf[pr][idx]);
                    if (t2 > 0)      Pm = __ldcg(&d_Pbuf[pr][idx - Gg]);
                    if (t2 < Tt - 1) Pp = __ldcg(&d_Pbuf[pr][idx + Gg]);
                    Rux = __ldcg(&d_Rup[idx]); Rdx = __ldcg(&d_Rdn[idx]);
                    dux = __ldcg(&d_dumax[idx]); ddx = __ldcg(&d_ddmax[idx]);
                    dui = __ldcg(&d_dumin[idx]); ddi = __ldcg(&d_ddmin[idx]);
                }
                #pragma unroll
                for (int cc = 0; cc < NCHB; ++cc) {
                    U7 += __ldcg(&d_U7P[(bt2*NCHB + cc)*Gg + g]);
                    U8 += __ldcg(&d_U8P[(bt2*NCHB + cc)*Gg + g]);
                }
                bg = bG[g]; pmn = pmin_[g]; pmx = pmax_[g];
            }
            float s1 = wsum(P), s3 = wsum(dux - ddx), s4 = wsum(dui - ddi);
            if (l == 0) { sred[w] = s1; sred[8+w] = s3; sred[16+w] = s4; }
            __syncthreads();
            if (tid == 0) {
                float a=0,c=0,d=0;
                #pragma unroll
                for (int i = 0; i < 8; i++) { a+=sred[i]; c+=sred[8+i]; d+=sred[16+i]; }
                float LSx = (it>0)?d_LSmax[bt2]:0.f, SPx = (it>0)?d_SPmax[bt2]:0.f;
                float LSi = (it>0)?d_LSmin[bt2]:0.f, SPi = (it>0)?d_SPmin[bt2]:0.f;
                shc[0] = a - fc[bt2];
                shc[1] = c + LSx - SPx - omx[bt2];
                shc[2] = d + LSi - SPi - omn[bt2];
                shc[3] = __ldcg(&d_WA[b2]); shc[4] = __ldcg(&d_WB[b2]);
                shc[5] = LSx; shc[6] = SPx;
            }
            __syncthreads();
            float r1 = shc[0], r3 = shc[1], r4 = shc[2], WA = shc[3], WB = shc[4];
            float qmx = 0.f, qmn = 0.f;
            if (act) {
                float rtu = 2.f*bg, rtd = 0.5f*bg;
                float r5  = fmaxf(P + Rux - pmx, 0.f);
                float r6  = fmaxf(pmn - P + Rdx, 0.f);
                float r9  = fmaxf(dux - Rux, 0.f), r10 = fmaxf(ddx - Rdx, 0.f);
                float r11 = fmaxf(dui - Rux, 0.f), r12 = fmaxf(ddi - Rdx, 0.f);
                float sl = 0.f, sr = 0.f;
                if (t2 > 0)      { float dp = P - Pm; float rl = fmaxf(fabsf(dp) - pmx, 0.f); sl = (dp > 0.f) ? rl : -rl; }
                if (t2 < Tt - 1) { float dp = Pp - P; float rl = fmaxf(fabsf(dp) - pmx, 0.f); sr = (dp > 0.f) ? rl : -rl; }
                float nP = P - LRc * (bg + TWO_RHO * (r1 + r5 - r6 + sl - sr));
                nP = fminf(fmaxf(nP, pmn), pmx);
                float nRu = fmaxf(Rux - LRc * (0.05f*bg + TWO_RHO * (r5 - U7 - r9 - r11)), 0.f);
                float nRd = fmaxf(Rdx - LRc * (0.02f*bg + TWO_RHO * (r6 - U8 - r10 - r12)), 0.f);
                float ndux = fmaxf(dux - LRc * (WA*rtu + TWO_RHO * ( r3 + r9 )), 0.f);
                float nddx = fmaxf(ddx - LRc * (WA*rtd + TWO_RHO * (-r3 + r10)), 0.f);
                float ndui = fmaxf(dui - LRc * (WB*rtu + TWO_RHO * ( r4 + r11)), 0.f);
                float nddi = fmaxf(ddi - LRc * (WB*rtd + TWO_RHO * (-r4 + r12)), 0.f);
                __stcg(&d_Pbuf[pw][idx], nP);
                __stcg(&d_Rup[idx], nRu); __stcg(&d_Rdn[idx], nRd);
                __stcg(&d_dumax[idx], ndux); __stcg(&d_ddmax[idx], nddx);
                __stcg(&d_dumin[idx], ndui); __stcg(&d_ddmin[idx], nddi);
                qmx = rtu*ndux + rtd*nddx;
                qmn = rtu*ndui + rtd*nddi;
            }
            if (tid == 0) {
                float LSi = (it>0)?d_LSmin[bt2]:0.f, SPi = (it>0)?d_SPmin[bt2]:0.f;
                float v;
                v = fmaxf(shc[5] - LRc*(WA*VOLLc + TWO_RHO*r3), 0.f); d_LSmax[bt2] = v; qmx += VOLLc*v;
                v = fmaxf(shc[6] - LRc*(WA*VOSPc - TWO_RHO*r3), 0.f); d_SPmax[bt2] = v; qmx += VOSPc*v;
                v = fmaxf(LSi    - LRc*(WB*VOLLc + TWO_RHO*r4), 0.f); d_LSmin[bt2] = v; qmn += VOLLc*v;
                v = fmaxf(SPi    - LRc*(WB*VOSPc - TWO_RHO*r4), 0.f); d_SPmin[bt2] = v; qmn += VOSPc*v;
            }
            qmx = wsum(qmx); qmn = wsum(qmn);
            if (l == 0) { sred[w] = qmx; sred[8+w] = qmn; }
            __syncthreads();
            if (tid == 0) {
                float X=0,Y=0;
                #pragma unroll
                for (int i = 0; i < 8; i++) { X+=sred[i]; Y+=sred[8+i]; }
                __stcg(&d_QmaxP[bt2], X);
                __stcg(&d_QminP[bt2], Y);
            }
        }

        grid_barrier();
    }

    // ================= finalize: blocks 0..7 =================
    if (blk < Bb) {
        int bf = blk;
        float s1 = 0.f;
        for (int i = tid; i < TG; i += 256) {
            int g = i % Gg, tt = i / Gg;
            float P  = __ldcg(&d_Pbuf[0][bf*TG + i]);
            float Rux = __ldcg(&d_Rup[bf*TG + i]);
            float Rdx = __ldcg(&d_Rdn[bf*TG + i]);
            float bg = bG[g];
            float C = bg * P + cG[g];
            int oi = bf*TG + g*Tt + tt;            // [b][g][t]
            out[oi] = P;
            out[BTG   + oi] = Rux;
            out[2*BTG + oi] = Rdx;
            out[3*BTG + oi] = C;
            s1 += C + 0.05f*bg*Rux + 0.02f*bg*Rdx;
        }
        float Qmax = 0.f, Qmin = 0.f;
        #pragma unroll 4
        for (int tt = 0; tt < Tt; ++tt) {
            Qmax += __ldcg(&d_QmaxP[bf*Tt + tt]);
            Qmin += __ldcg(&d_QminP[bf*Tt + tt]);
        }
        float gm = __ldcg(&d_gam[0][bf]);
        float ph = 0.f;
        if (tid < Nn) {
            float Qn = 0.f;
            #pragma unroll 4
            for (int tt = 0; tt < Tt; ++tt)
                Qn += __ldcg(&d_QnP[(bf*Tt + tt)*Nn + tid]);
            float Ap = Qmax - gm * __ldcg(&d_dmax[bf*Nn + tid]);
            float Bp = Qmin - gm * __ldcg(&d_dmin[bf*Nn + tid]);
            float phi = fmaxf(Qn, fmaxf(Ap, Bp));
            out[4*BTG + bf*Nn + tid] = phi;
            ph = phi;
        }
        s1 = wsum(s1); ph = wsum(ph);
        if (l == 0) { sred[w] = s1; sred[8+w] = ph; }
        __syncthreads();
        if (tid == 0) {
            float S = 0.f, PH = 0.f;
            #pragma unroll
            for (int i = 0; i < 8; i++) { S += sred[i]; PH += sred[8+i]; }
            out[4*BTG + BN + bf]      = gm;
            out[4*BTG + BN + Bb + bf] = S + PH / (float)Nn + eps_[bf] * gm;
        }
    }
}

extern "C" void kernel_launch(void* const* d_in, const int* in_sizes, int n_in,
                              void* d_out, int out_size) {
    const float* forecast = (const float*)d_in[0];  // [B,T]
    const float* omega    = (const float*)d_in[1];  // [B,N,T]
    const float* om_min   = (const float*)d_in[2];  // [B,T]
    const float* om_max   = (const float*)d_in[3];  // [B,T]
    const float* eps      = (const float*)d_in[4];  // [B]
    const float* pmin     = (const float*)d_in[5];  // [G]
    const float* pmax     = (const float*)d_in[6];  // [G]
    const float* bG       = (const float*)d_in[7];  // [G]
    const float* cG       = (const float*)d_in[8];  // [G]
    float* out = (float*)d_out;
    (void)in_sizes; (void)n_in; (void)out_size;

    solver<<<GRID, 256>>>(forecast, omega, om_min, om_max, eps,
                          pmin, pmax, bG, cG, out);
}

// round 12
// speedup vs baseline: 2.3992x; 1.2178x over previous
#include <cuda_runtime.h>
#include <cuda_bf16.h>

#define Bb 8
#define Nn 128
#define Gg 100
#define Tt 24
#define ITERS 40
#define LRc 2e-4f
#define TWO_RHO 20.0f
#define VOLLc 1000.0f
#define VOSPc 50.0f

#define NWRP 16             // warps per block
#define SPW  8              // scenarios per warp (16*8 = 128)
#define THR  512

#define TG   (Tt*Gg)        // 2400
#define BTG  (Bb*TG)        // 19200
#define BNTG (Bb*Nn*Tt*Gg)
#define BN   (Bb*Nn)        // 1024
#define BT   (Bb*Tt)        // 192
#define GRID BT             // 192 blocks, one per (b,t)

// ---------------- device state (cross-block only) ----------------
__device__ float d_dup[BNTG], d_ddn[BNTG];
__device__ float d_Pbuf[2][BTG];
__device__ float d_Rup[BTG], d_Rdn[BTG];          // written last iter only (finalize)
__device__ float d_QmaxP[BT], d_QminP[BT];
__device__ float d_QnP[BT*Nn];                    // [b][t][n]

// ---------------- grid barrier (single-wave, 192 blocks) ----------------
__device__ unsigned g_cnt = 0;
__device__ volatile unsigned g_gen = 0;

__device__ __forceinline__ void grid_barrier() {
    __syncthreads();
    if (threadIdx.x == 0) {
        __threadfence();
        unsigned gen = g_gen;
        if (atomicAdd(&g_cnt, 1u) == (unsigned)(GRID - 1)) {
            g_cnt = 0;
            __threadfence();
            g_gen = gen + 1u;
        } else {
            while (g_gen == gen) __nanosleep(16);
        }
        __threadfence();
    }
    __syncthreads();
}

__device__ __forceinline__ float wsum(float v) {
    #pragma unroll
    for (int o = 16; o; o >>= 1) v += __shfl_down_sync(0xffffffffu, v, o);
    return v;
}
__device__ __forceinline__ void wsum2x(float& a, float& b) {
    #pragma unroll
    for (int o = 16; o; o >>= 1) {
        a += __shfl_xor_sync(0xffffffffu, a, o);
        b += __shfl_xor_sync(0xffffffffu, b, o);
    }
}
__device__ __forceinline__ void wsum2d(float& a, float& b) {
    #pragma unroll
    for (int o = 16; o; o >>= 1) {
        a += __shfl_down_sync(0xffffffffu, a, o);
        b += __shfl_down_sync(0xffffffffu, b, o);
    }
}

// ---------------- the whole solver, one launch ----------------
__global__ __launch_bounds__(THR, 2) void solver(
    const float* __restrict__ fc,   const float* __restrict__ omega,
    const float* __restrict__ omn,  const float* __restrict__ omx,
    const float* __restrict__ eps_, const float* __restrict__ pmin_,
    const float* __restrict__ pmax_,const float* __restrict__ bG,
    const float* __restrict__ cG,   float* __restrict__ out)
{
    int bt = blockIdx.x, tid = threadIdx.x;
    int w = tid >> 5, l = tid & 31;
    int t = bt % Tt, b = bt / Tt;

    // persistent block-local state
    __shared__ float shLSst[Nn], shSPst[Nn], shOM[Nn], shWQ[Nn];
    __shared__ float shU7[NWRP*104], shU8[NWRP*104];
    __shared__ float sRu[Gg], sRd[Gg];
    __shared__ float sdux[Gg], sddx[Gg], sdui[Gg], sddi[Gg];
    __shared__ float sred[32];
    __shared__ float shQm[Tt], shQi[Tt];
    __shared__ float shc[8];
    __shared__ float shGamma, sLSx, sSPx, sLSi, sSPi;
    __shared__ float sFC, sOMN, sOMX, sEPS;

    // ---- per-thread constants ----
    float bgv[4];
    #pragma unroll
    for (int j = 0; j < 4; ++j) {
        int g = l + 32*j;
        bgv[j] = (g < Gg) ? bG[g] : 0.f;
    }
    float bgs = 0.f, pmnv = 0.f, pmxv = 0.f;
    if (tid < Gg) { bgs = bG[tid]; pmnv = pmin_[tid]; pmxv = pmax_[tid]; }

    // ---- init block-local state ----
    float dmx = 0.f, dmn = 0.f;
    if (tid < Nn) {
        shLSst[tid] = 0.f; shSPst[tid] = 0.f;
        shOM[tid] = omega[(b*Nn + tid)*Tt + t];
        #pragma unroll 4
        for (int tt = 0; tt < Tt; ++tt) {
            float om = omega[(b*Nn + tid)*Tt + tt];
            dmx += omx[b*Tt + tt] - om;
            dmn += om - omn[b*Tt + tt];
        }
    }
    if (tid < Gg) {
        sRu[tid] = 0.f; sRd[tid] = 0.f;
        sdux[tid] = 0.f; sddx[tid] = 0.f; sdui[tid] = 0.f; sddi[tid] = 0.f;
    }
    if (tid == 0) {
        shGamma = 0.f; sLSx = 0.f; sSPx = 0.f; sLSi = 0.f; sSPi = 0.f;
        sFC = fc[bt]; sOMN = omn[bt]; sOMX = omx[bt]; sEPS = eps_[b];
    }
    __syncthreads();

    const long nstr = (long)Tt * Gg;

    for (int it = 0; it < ITERS; ++it) {
        int pr = it & 1, pw = pr ^ 1;

        // ============ prologue: phi weights + gamma (all local) ============
        float gamma_old = shGamma;
        if (it > 0) {
            if (tid < Tt) shQm[tid] = __ldcg(&d_QmaxP[b*Tt + tid]);
            else if (tid >= 32 && tid < 32 + Tt) shQi[tid-32] = __ldcg(&d_QminP[b*Tt + tid - 32]);
        }
        __syncthreads();

        float wa = 0.f, wb = 0.f;
        if (tid < Nn) {
            float wq;
            if (it == 0) { wq = 0.5f; wa = 0.25f; wb = 0.25f; }
            else {
                float Qmax = 0.f, Qmin = 0.f;
                #pragma unroll 8
                for (int tt = 0; tt < Tt; ++tt) { Qmax += shQm[tt]; Qmin += shQi[tt]; }
                float Qn = 0.f;
                #pragma unroll 4
                for (int tt = 0; tt < Tt; ++tt)
                    Qn += __ldcg(&d_QnP[(b*Tt + tt)*Nn + tid]);
                float Ap = Qmax - gamma_old * dmx;
                float Bp = Qmin - gamma_old * dmn;
                float M  = fmaxf(Ap, Bp);
                wq = (Qn > M) ? 1.f : ((Qn == M) ? 0.5f : 0.f);
                float aw = (Ap > Bp) ? 1.f : ((Ap == Bp) ? 0.5f : 0.f);
                float bw = (Bp > Ap) ? 1.f : ((Ap == Bp) ? 0.5f : 0.f);
                float wm = 1.f - wq;
                wa = wm * aw; wb = wm * bw;
            }
            shWQ[tid] = wq * (1.f / (float)Nn);
        }
        if (w < 4) {
            float v0 = wsum(wa), v1 = wsum(wb), v2 = wsum(wa * dmx), v3 = wsum(wb * dmn);
            if (l == 0) { sred[w] = v0; sred[4+w] = v1; sred[8+w] = v2; sred[12+w] = v3; }
        }
        __syncthreads();
        if (tid == 0) {
            float A = sred[0]+sred[1]+sred[2]+sred[3];
            float B = sred[4]+sred[5]+sred[6]+sred[7];
            float C = sred[8]+sred[9]+sred[10]+sred[11];
            float D = sred[12]+sred[13]+sred[14]+sred[15];
            float inv = 1.f / (float)Nn;
            shc[3] = A*inv; shc[4] = B*inv;
            shGamma = fmaxf(gamma_old - LRc * (sEPS - C*inv - D*inv), 0.f);
        }
        __syncthreads();

        // ============ big phase: warp w handles scenarios w*8 .. w*8+7 =====
        float u7a[4] = {0,0,0,0}, u8a[4] = {0,0,0,0};
        long base0 = ((long)(b*Nn + w*SPW)*Tt + t)*Gg;

        #pragma unroll
        for (int sp = 0; sp < SPW/2; ++sp) {
            int s0 = 2*sp, s1 = 2*sp + 1;
            long ba0 = base0 + s0*nstr, ba1 = base0 + s1*nstr;
            float du0[4], dd0[4], du1[4], dd1[4];
            #pragma unroll
            for (int j = 0; j < 4; ++j) {
                int g = l + 32*j;
                bool a = (g < Gg) && (it > 0);
                du0[j] = a ? d_dup[ba0 + g] : 0.f;
                dd0[j] = a ? d_ddn[ba0 + g] : 0.f;
                du1[j] = a ? d_dup[ba1 + g] : 0.f;
                dd1[j] = a ? d_ddn[ba1 + g] : 0.f;
            }
            float r20 = (du0[0]-dd0[0]) + (du0[1]-dd0[1]) + (du0[2]-dd0[2]) + (du0[3]-dd0[3]);
            float r21 = (du1[0]-dd1[0]) + (du1[1]-dd1[1]) + (du1[2]-dd1[2]) + (du1[3]-dd1[3]);
            wsum2x(r20, r21);
            int si0 = w*SPW + s0, si1 = si0 + 1;
            r20 += shLSst[si0] - shSPst[si0] - shOM[si0];
            r21 += shLSst[si1] - shSPst[si1] - shOM[si1];
            float wq0 = shWQ[si0], wq1 = shWQ[si1];
            float q0 = 0.f, q1 = 0.f;
            #pragma unroll
            for (int j = 0; j < 4; ++j) {
                int g = l + 32*j;
                if (g < Gg) {
                    float rtu = 2.0f * bgv[j], rtd = 0.5f * bgv[j];
                    float Ruj = sRu[g], Rdj = sRd[g];
                    float rl7 = fmaxf(du0[j] - Ruj, 0.f);
                    float rl8 = fmaxf(dd0[j] - Rdj, 0.f);
                    u7a[j] += rl7; u8a[j] += rl8;
                    float ndu = fmaxf(du0[j] - LRc * (wq0*rtu + TWO_RHO * (r20 + rl7)), 0.f);
                    float ndd = fmaxf(dd0[j] - LRc * (wq0*rtd + TWO_RHO * (rl8 - r20)), 0.f);
                    d_dup[ba0 + g] = ndu; d_ddn[ba0 + g] = ndd;
                    q0 += rtu*ndu + rtd*ndd;
                    rl7 = fmaxf(du1[j] - Ruj, 0.f);
                    rl8 = fmaxf(dd1[j] - Rdj, 0.f);
                    u7a[j] += rl7; u8a[j] += rl8;
                    ndu = fmaxf(du1[j] - LRc * (wq1*rtu + TWO_RHO * (r21 + rl7)), 0.f);
                    ndd = fmaxf(dd1[j] - LRc * (wq1*rtd + TWO_RHO * (rl8 - r21)), 0.f);
                    d_dup[ba1 + g] = ndu; d_ddn[ba1 + g] = ndd;
                    q1 += rtu*ndu + rtd*ndd;
                }
            }
            float qls0 = 0.f, qls1 = 0.f;
            if (l == 0) {
                float lsn = fmaxf(shLSst[si0] - LRc * (wq0*VOLLc + TWO_RHO*r20), 0.f);
                float spn = fmaxf(shSPst[si0] - LRc * (wq0*VOSPc - TWO_RHO*r20), 0.f);
                shLSst[si0] = lsn; shSPst[si0] = spn;
                qls0 = VOLLc*lsn + VOSPc*spn;
                lsn = fmaxf(shLSst[si1] - LRc * (wq1*VOLLc + TWO_RHO*r21), 0.f);
                spn = fmaxf(shSPst[si1] - LRc * (wq1*VOSPc - TWO_RHO*r21), 0.f);
                shLSst[si1] = lsn; shSPst[si1] = spn;
                qls1 = VOLLc*lsn + VOSPc*spn;
            }
            wsum2d(q0, q1);
            if (l == 0) {
                __stcg(&d_QnP[bt*Nn + si0], q0 + qls0);
                __stcg(&d_QnP[bt*Nn + si1], q1 + qls1);
            }
        }
        #pragma unroll
        for (int j = 0; j < 4; ++j) {
            int g = l + 32*j;
            if (g < Gg) { shU7[w*104 + g] = u7a[j]; shU8[w*104 + g] = u8a[j]; }
        }
        __syncthreads();

        // ============ small phase (same block, fused) ============
        {
            int g = tid;
            bool act = (g < Gg);
            int idx = bt*Gg + g;
            float P=0,Pm=0,Pp=0,Rux=0,Rdx=0,dux=0,ddx=0,dui=0,ddi=0,U7=0,U8=0;
            if (act) {
                if (it == 0) { float pv = 0.5f*(pmnv + pmxv); P = pv; Pm = pv; Pp = pv; }
                else {
                    P = __ldcg(&d_Pbuf[pr][idx]);
                    if (t > 0)      Pm = __ldcg(&d_Pbuf[pr][idx - Gg]);
                    if (t < Tt - 1) Pp = __ldcg(&d_Pbuf[pr][idx + Gg]);
                }
                Rux = sRu[g]; Rdx = sRd[g];
                dux = sdux[g]; ddx = sddx[g]; dui = sdui[g]; ddi = sddi[g];
                #pragma unroll
                for (int ww = 0; ww < NWRP; ++ww) {
                    U7 += shU7[ww*104 + g];
                    U8 += shU8[ww*104 + g];
                }
            }
            float s1 = 0.f, s3 = 0.f, s4 = 0.f;
            if (act) { s1 = P; s3 = dux - ddx; s4 = dui - ddi; }
            if (w < 4) {
                s1 = wsum(s1); s3 = wsum(s3); s4 = wsum(s4);
                if (l == 0) { sred[w] = s1; sred[4+w] = s3; sred[8+w] = s4; }
            }
            __syncthreads();
            if (tid == 0) {
                shc[0] = sred[0]+sred[1]+sred[2]+sred[3] - sFC;
                shc[1] = sred[4]+sred[5]+sred[6]+sred[7] + sLSx - sSPx - sOMX;
                shc[2] = sred[8]+sred[9]+sred[10]+sred[11] + sLSi - sSPi - sOMN;
            }
            __syncthreads();
            float r1 = shc[0], r3 = shc[1], r4 = shc[2], WA = shc[3], WB = shc[4];
            float qmx = 0.f, qmn = 0.f;
            if (act) {
                float rtu = 2.f*bgs, rtd = 0.5f*bgs;
                float r5  = fmaxf(P + Rux - pmxv, 0.f);
                float r6  = fmaxf(pmnv - P + Rdx, 0.f);
                float r9  = fmaxf(dux - Rux, 0.f), r10 = fmaxf(ddx - Rdx, 0.f);
                float r11 = fmaxf(dui - Rux, 0.f), r12 = fmaxf(ddi - Rdx, 0.f);
                float sl = 0.f, sr = 0.f;
                if (t > 0)      { float dp = P - Pm; float rl = fmaxf(fabsf(dp) - pmxv, 0.f); sl = (dp > 0.f) ? rl : -rl; }
                if (t < Tt - 1) { float dp = Pp - P; float rl = fmaxf(fabsf(dp) - pmxv, 0.f); sr = (dp > 0.f) ? rl : -rl; }
                float nP = P - LRc * (bgs + TWO_RHO * (r1 + r5 - r6 + sl - sr));
                nP = fminf(fmaxf(nP, pmnv), pmxv);
                float nRu = fmaxf(Rux - LRc * (0.05f*bgs + TWO_RHO * (r5 - U7 - r9 - r11)), 0.f);
                float nRd = fmaxf(Rdx - LRc * (0.02f*bgs + TWO_RHO * (r6 - U8 - r10 - r12)), 0.f);
                float ndux = fmaxf(dux - LRc * (WA*rtu + TWO_RHO * ( r3 + r9 )), 0.f);
                float nddx = fmaxf(ddx - LRc * (WA*rtd + TWO_RHO * (-r3 + r10)), 0.f);
                float ndui = fmaxf(dui - LRc * (WB*rtu + TWO_RHO * ( r4 + r11)), 0.f);
                float nddi = fmaxf(ddi - LRc * (WB*rtd + TWO_RHO * (-r4 + r12)), 0.f);
                __stcg(&d_Pbuf[pw][idx], nP);
                sRu[g] = nRu; sRd[g] = nRd;
                sdux[g] = ndux; sddx[g] = nddx; sdui[g] = ndui; sddi[g] = nddi;
                if (it == ITERS - 1) { __stcg(&d_Rup[idx], nRu); __stcg(&d_Rdn[idx], nRd); }
                qmx = rtu*ndux + rtd*nddx;
                qmn = rtu*ndui + rtd*nddi;
            }
            if (tid == 0) {
                float v;
                v = fmaxf(sLSx - LRc*(WA*VOLLc + TWO_RHO*r3), 0.f); sLSx = v; qmx += VOLLc*v;
                v = fmaxf(sSPx - LRc*(WA*VOSPc - TWO_RHO*r3), 0.f); sSPx = v; qmx += VOSPc*v;
                v = fmaxf(sLSi - LRc*(WB*VOLLc + TWO_RHO*r4), 0.f); sLSi = v; qmn += VOLLc*v;
                v = fmaxf(sSPi - LRc*(WB*VOSPc - TWO_RHO*r4), 0.f); sSPi = v; qmn += VOSPc*v;
            }
            if (w < 4) {
                qmx = wsum(qmx); qmn = wsum(qmn);
                if (l == 0) { sred[16+w] = qmx; sred[20+w] = qmn; }
            }
            __syncthreads();
            if (tid == 0) {
                __stcg(&d_QmaxP[bt], sred[16]+sred[17]+sred[18]+sred[19]);
                __stcg(&d_QminP[bt], sred[20]+sred[21]+sred[22]+sred[23]);
            }
        }

        grid_barrier();
    }

    // ============ finalize: t==0 blocks (one per batch) ============
    if (t == 0) {
        int bf = b;
        float s1 = 0.f;
        for (int i = tid; i < TG; i += THR) {
            int g = i % Gg, tt = i / Gg;
            float P   = __ldcg(&d_Pbuf[0][bf*TG + i]);
            float Rux = __ldcg(&d_Rup[bf*TG + i]);
            float Rdx = __ldcg(&d_Rdn[bf*TG + i]);
            float bg = bG[g];
            float C = bg * P + cG[g];
            int oi = bf*TG + g*Tt + tt;            // [b][g][t]
            out[oi] = P;
            out[BTG   + oi] = Rux;
            out[2*BTG + oi] = Rdx;
            out[3*BTG + oi] = C;
            s1 += C + 0.05f*bg*Rux + 0.02f*bg*Rdx;
        }
        float Qmax = 0.f, Qmin = 0.f;
        #pragma unroll 4
        for (int tt = 0; tt < Tt; ++tt) {
            Qmax += __ldcg(&d_QmaxP[bf*Tt + tt]);
            Qmin += __ldcg(&d_QminP[bf*Tt + tt]);
        }
        float gm = shGamma;
        float ph = 0.f;
        if (tid < Nn) {
            float Qn = 0.f;
            #pragma unroll 4
            for (int tt = 0; tt < Tt; ++tt)
                Qn += __ldcg(&d_QnP[(bf*Tt + tt)*Nn + tid]);
            float Ap = Qmax - gm * dmx;
            float Bp = Qmin - gm * dmn;
            float phi = fmaxf(Qn, fmaxf(Ap, Bp));
            out[4*BTG + bf*Nn + tid] = phi;
            ph = phi;
        }
        s1 = wsum(s1); ph = wsum(ph);
        if (l == 0) { sred[w] = s1; sred[16 + w] = ph; }
        __syncthreads();
        if (tid == 0) {
            float S = 0.f, PH = 0.f;
            #pragma unroll
            for (int i = 0; i < 16; i++) S += sred[i];
            #pragma unroll
            for (int i = 0; i < 4; i++) PH += sred[16+i];
            out[4*BTG + BN + bf]      = gm;
            out[4*BTG + BN + Bb + bf] = S + PH / (float)Nn + sEPS * gm;
        }
    }
}

extern "C" void kernel_launch(void* const* d_in, const int* in_sizes, int n_in,
                              void* d_out, int out_size) {
    const float* forecast = (const float*)d_in[0];  // [B,T]
    const float* omega    = (const float*)d_in[1];  // [B,N,T]
    const float* om_min   = (const float*)d_in[2];  // [B,T]
    const float* om_max   = (const float*)d_in[3];  // [B,T]
    const float* eps      = (const float*)d_in[4];  // [B]
    const float* pmin     = (const float*)d_in[5];  // [G]
    const float* pmax     = (const float*)d_in[6];  // [G]
    const float* bG       = (const float*)d_in[7];  // [G]
    const float* cG       = (const float*)d_in[8];  // [G]
    float* out = (float*)d_out;
    (void)in_sizes; (void)n_in; (void)out_size;

    solver<<<GRID, THR>>>(forecast, omega, om_min, om_max, eps,
                          pmin, pmax, bG, cG, out);
}

// round 13
// speedup vs baseline: 2.7032x; 1.1267x over previous
#include <cuda_runtime.h>
#include <cuda_bf16.h>

#define Bb 8
#define Nn 128
#define Gg 100
#define Tt 24
#define ITERS 40
#define LRc 2e-4f
#define TWO_RHO 20.0f
#define VOLLc 1000.0f
#define VOSPc 50.0f

#define NWRP 16             // warps per block
#define SPW  8              // scenarios per warp (16*8 = 128)
#define THR  512

#define TG   (Tt*Gg)        // 2400
#define BTG  (Bb*TG)        // 19200
#define BN   (Bb*Nn)        // 1024
#define BT   (Bb*Tt)        // 192
#define GRID BT             // 192 blocks, one per (b,t)

// dynamic smem layout (floats)
#define DUP_OFF 0
#define DDN_OFF 12800
#define U7_OFF  25600
#define U8_OFF  26000
#define DYN_FLOATS 26400    // 105,600 bytes

// ---------------- device state (cross-block only) ----------------
__device__ float d_Pbuf[2][BTG];
__device__ float d_Rup[BTG], d_Rdn[BTG];          // written last iter only
__device__ float d_QmaxP[BT], d_QminP[BT];
__device__ float d_QnP[BT*Nn];                    // [b][t][n]

// ---------------- grid barrier (single-wave, 192 blocks) ----------------
__device__ unsigned g_cnt = 0;
__device__ volatile unsigned g_gen = 0;

__device__ __forceinline__ void grid_barrier() {
    __syncthreads();
    if (threadIdx.x == 0) {
        __threadfence();
        unsigned gen = g_gen;
        if (atomicAdd(&g_cnt, 1u) == (unsigned)(GRID - 1)) {
            g_cnt = 0;
            __threadfence();
            g_gen = gen + 1u;
        } else {
            while (g_gen == gen) __nanosleep(16);
        }
        __threadfence();
    }
    __syncthreads();
}

__device__ __forceinline__ float wsum(float v) {
    #pragma unroll
    for (int o = 16; o; o >>= 1) v += __shfl_down_sync(0xffffffffu, v, o);
    return v;
}
__device__ __forceinline__ void wsum2x(float& a, float& b) {
    #pragma unroll
    for (int o = 16; o; o >>= 1) {
        a += __shfl_xor_sync(0xffffffffu, a, o);
        b += __shfl_xor_sync(0xffffffffu, b, o);
    }
}
__device__ __forceinline__ void wsum2d(float& a, float& b) {
    #pragma unroll
    for (int o = 16; o; o >>= 1) {
        a += __shfl_down_sync(0xffffffffu, a, o);
        b += __shfl_down_sync(0xffffffffu, b, o);
    }
}

// ---------------- the whole solver, one launch ----------------
__global__ __launch_bounds__(THR, 2) void solver(
    const float* __restrict__ fc,   const float* __restrict__ omega,
    const float* __restrict__ omn,  const float* __restrict__ omx,
    const float* __restrict__ eps_, const float* __restrict__ pmin_,
    const float* __restrict__ pmax_,const float* __restrict__ bG,
    const float* __restrict__ cG,   float* __restrict__ out)
{
    extern __shared__ float dyn[];
    float* dup  = dyn + DUP_OFF;     // [128][100]
    float* ddn  = dyn + DDN_OFF;     // [128][100]
    float* sU7p = dyn + U7_OFF;      // [4][100]
    float* sU8p = dyn + U8_OFF;      // [4][100]

    int bt = blockIdx.x, tid = threadIdx.x;
    int w = tid >> 5, l = tid & 31;
    int t = bt % Tt, b = bt / Tt;

    // block-local persistent state (static smem, ~5 KB)
    __shared__ float shLSst[Nn], shSPst[Nn], shOM[Nn], shWQ[Nn];
    __shared__ float sRu[Gg], sRd[Gg];
    __shared__ float sdux[Gg], sddx[Gg], sdui[Gg], sddi[Gg];
    __shared__ float sred[32];
    __shared__ float shQm[Tt], shQi[Tt];
    __shared__ float shc[8];
    __shared__ float shGamma, sLSx, sSPx, sLSi, sSPi;
    __shared__ float sFC, sOMN, sOMX, sEPS;

    // per-thread constants
    float bgv[4];
    #pragma unroll
    for (int j = 0; j < 4; ++j) {
        int g = l + 32*j;
        bgv[j] = (g < Gg) ? bG[g] : 0.f;
    }
    float bgs = 0.f, pmnv = 0.f, pmxv = 0.f;
    if (tid < Gg) { bgs = bG[tid]; pmnv = pmin_[tid]; pmxv = pmax_[tid]; }

    // ---- init ----
    for (int i = tid; i < 12800; i += THR) { dup[i] = 0.f; ddn[i] = 0.f; }
    float dmx = 0.f, dmn = 0.f;
    if (tid < Nn) {
        shLSst[tid] = 0.f; shSPst[tid] = 0.f;
        shOM[tid] = omega[(b*Nn + tid)*Tt + t];
        #pragma unroll 4
        for (int tt = 0; tt < Tt; ++tt) {
            float om = omega[(b*Nn + tid)*Tt + tt];
            dmx += omx[b*Tt + tt] - om;
            dmn += om - omn[b*Tt + tt];
        }
    }
    if (tid < Gg) {
        sRu[tid] = 0.f; sRd[tid] = 0.f;
        sdux[tid] = 0.f; sddx[tid] = 0.f; sdui[tid] = 0.f; sddi[tid] = 0.f;
    }
    if (tid == 0) {
        shGamma = 0.f; sLSx = 0.f; sSPx = 0.f; sLSi = 0.f; sSPi = 0.f;
        sFC = fc[bt]; sOMN = omn[bt]; sOMX = omx[bt]; sEPS = eps_[b];
    }
    __syncthreads();

    for (int it = 0; it < ITERS; ++it) {
        int pr = it & 1, pw = pr ^ 1;

        // ============ prologue: phi weights + gamma ============
        float gamma_old = shGamma;
        if (it > 0) {
            if (tid < Tt) shQm[tid] = __ldcg(&d_QmaxP[b*Tt + tid]);
            else if (tid >= 32 && tid < 32 + Tt) shQi[tid-32] = __ldcg(&d_QminP[b*Tt + tid - 32]);
        }
        __syncthreads();

        float wa = 0.f, wb = 0.f;
        if (tid < Nn) {
            float wq;
            if (it == 0) { wq = 0.5f; wa = 0.25f; wb = 0.25f; }
            else {
                float Qmax = 0.f, Qmin = 0.f;
                #pragma unroll 8
                for (int tt = 0; tt < Tt; ++tt) { Qmax += shQm[tt]; Qmin += shQi[tt]; }
                float Qn = 0.f;
                #pragma unroll 8
                for (int tt = 0; tt < Tt; ++tt)
                    Qn += __ldcg(&d_QnP[(b*Tt + tt)*Nn + tid]);
                float Ap = Qmax - gamma_old * dmx;
                float Bp = Qmin - gamma_old * dmn;
                float M  = fmaxf(Ap, Bp);
                wq = (Qn > M) ? 1.f : ((Qn == M) ? 0.5f : 0.f);
                float aw = (Ap > Bp) ? 1.f : ((Ap == Bp) ? 0.5f : 0.f);
                float bw = (Bp > Ap) ? 1.f : ((Ap == Bp) ? 0.5f : 0.f);
                float wm = 1.f - wq;
                wa = wm * aw; wb = wm * bw;
            }
            shWQ[tid] = wq * (1.f / (float)Nn);
        }
        if (w < 4) {
            float v0 = wsum(wa), v1 = wsum(wb), v2 = wsum(wa * dmx), v3 = wsum(wb * dmn);
            if (l == 0) { sred[w] = v0; sred[4+w] = v1; sred[8+w] = v2; sred[12+w] = v3; }
        }
        __syncthreads();
        if (tid == 0) {
            float A = sred[0]+sred[1]+sred[2]+sred[3];
            float B = sred[4]+sred[5]+sred[6]+sred[7];
            float C = sred[8]+sred[9]+sred[10]+sred[11];
            float D = sred[12]+sred[13]+sred[14]+sred[15];
            float inv = 1.f / (float)Nn;
            shc[3] = A*inv; shc[4] = B*inv;
            shGamma = fmaxf(gamma_old - LRc * (sEPS - C*inv - D*inv), 0.f);
        }

        // ============ U7/U8 pass (old dup vs old Ru), thread=(g,quarter) ====
        if (tid < 400) {
            int g = tid % Gg, q = tid / Gg;
            float Rux = sRu[g], Rdx = sRd[g];
            float u7 = 0.f, u8 = 0.f;
            int rb = q*32*Gg + g;
            #pragma unroll 8
            for (int n = 0; n < 32; ++n) {
                u7 += fmaxf(dup[rb + n*Gg] - Rux, 0.f);
                u8 += fmaxf(ddn[rb + n*Gg] - Rdx, 0.f);
            }
            sU7p[q*Gg + g] = u7;
            sU8p[q*Gg + g] = u8;
        }
        __syncthreads();

        // ============ big phase: warp w -> scenarios w*8..w*8+7 (all smem) ==
        #pragma unroll
        for (int sp = 0; sp < SPW/2; ++sp) {
            int si0 = w*SPW + 2*sp, si1 = si0 + 1;
            int r0 = si0*Gg, r1 = si1*Gg;
            float du0[4], dd0[4], du1[4], dd1[4];
            #pragma unroll
            for (int j = 0; j < 4; ++j) {
                int g = l + 32*j;
                bool a = (g < Gg);
                du0[j] = a ? dup[r0 + g] : 0.f;
                dd0[j] = a ? ddn[r0 + g] : 0.f;
                du1[j] = a ? dup[r1 + g] : 0.f;
                dd1[j] = a ? ddn[r1 + g] : 0.f;
            }
            float r20 = (du0[0]-dd0[0]) + (du0[1]-dd0[1]) + (du0[2]-dd0[2]) + (du0[3]-dd0[3]);
            float r21 = (du1[0]-dd1[0]) + (du1[1]-dd1[1]) + (du1[2]-dd1[2]) + (du1[3]-dd1[3]);
            wsum2x(r20, r21);
            r20 += shLSst[si0] - shSPst[si0] - shOM[si0];
            r21 += shLSst[si1] - shSPst[si1] - shOM[si1];
            float wq0 = shWQ[si0], wq1 = shWQ[si1];
            float q0 = 0.f, q1 = 0.f;
            #pragma unroll
            for (int j = 0; j < 4; ++j) {
                int g = l + 32*j;
                if (g < Gg) {
                    float rtu = 2.0f * bgv[j], rtd = 0.5f * bgv[j];
                    float Ruj = sRu[g], Rdj = sRd[g];
                    float rl7 = fmaxf(du0[j] - Ruj, 0.f);
                    float rl8 = fmaxf(dd0[j] - Rdj, 0.f);
                    float ndu = fmaxf(du0[j] - LRc * (wq0*rtu + TWO_RHO * (r20 + rl7)), 0.f);
                    float ndd = fmaxf(dd0[j] - LRc * (wq0*rtd + TWO_RHO * (rl8 - r20)), 0.f);
                    dup[r0 + g] = ndu; ddn[r0 + g] = ndd;
                    q0 += rtu*ndu + rtd*ndd;
                    rl7 = fmaxf(du1[j] - Ruj, 0.f);
                    rl8 = fmaxf(dd1[j] - Rdj, 0.f);
                    ndu = fmaxf(du1[j] - LRc * (wq1*rtu + TWO_RHO * (r21 + rl7)), 0.f);
                    ndd = fmaxf(dd1[j] - LRc * (wq1*rtd + TWO_RHO * (rl8 - r21)), 0.f);
                    dup[r1 + g] = ndu; ddn[r1 + g] = ndd;
                    q1 += rtu*ndu + rtd*ndd;
                }
            }
            float qls0 = 0.f, qls1 = 0.f;
            if (l == 0) {
                float lsn = fmaxf(shLSst[si0] - LRc * (wq0*VOLLc + TWO_RHO*r20), 0.f);
                float spn = fmaxf(shSPst[si0] - LRc * (wq0*VOSPc - TWO_RHO*r20), 0.f);
                shLSst[si0] = lsn; shSPst[si0] = spn;
                qls0 = VOLLc*lsn + VOSPc*spn;
                lsn = fmaxf(shLSst[si1] - LRc * (wq1*VOLLc + TWO_RHO*r21), 0.f);
                spn = fmaxf(shSPst[si1] - LRc * (wq1*VOSPc - TWO_RHO*r21), 0.f);
                shLSst[si1] = lsn; shSPst[si1] = spn;
                qls1 = VOLLc*lsn + VOSPc*spn;
            }
            wsum2d(q0, q1);
            if (l == 0) {
                __stcg(&d_QnP[bt*Nn + si0], q0 + qls0);
                __stcg(&d_QnP[bt*Nn + si1], q1 + qls1);
            }
        }
        __syncthreads();   // big done before small mutates sRu/sRd

        // ============ small phase (fused, same block) ============
        {
            int g = tid;
            bool act = (g < Gg);
            int idx = bt*Gg + g;
            float P=0,Pm=0,Pp=0,Rux=0,Rdx=0,dux=0,ddx=0,dui=0,ddi=0,U7=0,U8=0;
            if (act) {
                if (it == 0) { float pv = 0.5f*(pmnv + pmxv); P = pv; Pm = pv; Pp = pv; }
                else {
                    P = __ldcg(&d_Pbuf[pr][idx]);
                    if (t > 0)      Pm = __ldcg(&d_Pbuf[pr][idx - Gg]);
                    if (t < Tt - 1) Pp = __ldcg(&d_Pbuf[pr][idx + Gg]);
                }
                Rux = sRu[g]; Rdx = sRd[g];
                dux = sdux[g]; ddx = sddx[g]; dui = sdui[g]; ddi = sddi[g];
                U7 = sU7p[g] + sU7p[Gg+g] + sU7p[2*Gg+g] + sU7p[3*Gg+g];
                U8 = sU8p[g] + sU8p[Gg+g] + sU8p[2*Gg+g] + sU8p[3*Gg+g];
            }
            float s1 = 0.f, s3 = 0.f, s4 = 0.f;
            if (act) { s1 = P; s3 = dux - ddx; s4 = dui - ddi; }
            if (w < 4) {
                s1 = wsum(s1); s3 = wsum(s3); s4 = wsum(s4);
                if (l == 0) { sred[16+w] = s1; sred[20+w] = s3; sred[24+w] = s4; }
            }
            __syncthreads();
            if (tid == 0) {
                shc[0] = sred[16]+sred[17]+sred[18]+sred[19] - sFC;
                shc[1] = sred[20]+sred[21]+sred[22]+sred[23] + sLSx - sSPx - sOMX;
                shc[2] = sred[24]+sred[25]+sred[26]+sred[27] + sLSi - sSPi - sOMN;
            }
            __syncthreads();
            float r1 = shc[0], r3 = shc[1], r4 = shc[2], WA = shc[3], WB = shc[4];
            float qmx = 0.f, qmn = 0.f;
            if (act) {
                float rtu = 2.f*bgs, rtd = 0.5f*bgs;
                float r5  = fmaxf(P + Rux - pmxv, 0.f);
                float r6  = fmaxf(pmnv - P + Rdx, 0.f);
                float r9  = fmaxf(dux - Rux, 0.f), r10 = fmaxf(ddx - Rdx, 0.f);
                float r11 = fmaxf(dui - Rux, 0.f), r12 = fmaxf(ddi - Rdx, 0.f);
                float sl = 0.f, sr = 0.f;
                if (t > 0)      { float dp = P - Pm; float rl = fmaxf(fabsf(dp) - pmxv, 0.f); sl = (dp > 0.f) ? rl : -rl; }
                if (t < Tt - 1) { float dp = Pp - P; float rl = fmaxf(fabsf(dp) - pmxv, 0.f); sr = (dp > 0.f) ? rl : -rl; }
                float nP = P - LRc * (bgs + TWO_RHO * (r1 + r5 - r6 + sl - sr));
                nP = fminf(fmaxf(nP, pmnv), pmxv);
                float nRu = fmaxf(Rux - LRc * (0.05f*bgs + TWO_RHO * (r5 - U7 - r9 - r11)), 0.f);
                float nRd = fmaxf(Rdx - LRc * (0.02f*bgs + TWO_RHO * (r6 - U8 - r10 - r12)), 0.f);
                float ndux = fmaxf(dux - LRc * (WA*rtu + TWO_RHO * ( r3 + r9 )), 0.f);
                float nddx = fmaxf(ddx - LRc * (WA*rtd + TWO_RHO * (-r3 + r10)), 0.f);
                float ndui = fmaxf(dui - LRc * (WB*rtu + TWO_RHO * ( r4 + r11)), 0.f);
                float nddi = fmaxf(ddi - LRc * (WB*rtd + TWO_RHO * (-r4 + r12)), 0.f);
                __stcg(&d_Pbuf[pw][idx], nP);
                sRu[g] = nRu; sRd[g] = nRd;
                sdux[g] = ndux; sddx[g] = nddx; sdui[g] = ndui; sddi[g] = nddi;
                if (it == ITERS - 1) { __stcg(&d_Rup[idx], nRu); __stcg(&d_Rdn[idx], nRd); }
                qmx = rtu*ndux + rtd*nddx;
                qmn = rtu*ndui + rtd*nddi;
            }
            if (tid == 0) {
                float v;
                v = fmaxf(sLSx - LRc*(WA*VOLLc + TWO_RHO*r3), 0.f); sLSx = v; qmx += VOLLc*v;
                v = fmaxf(sSPx - LRc*(WA*VOSPc - TWO_RHO*r3), 0.f); sSPx = v; qmx += VOSPc*v;
                v = fmaxf(sLSi - LRc*(WB*VOLLc + TWO_RHO*r4), 0.f); sLSi = v; qmn += VOLLc*v;
                v = fmaxf(sSPi - LRc*(WB*VOSPc - TWO_RHO*r4), 0.f); sSPi = v; qmn += VOSPc*v;
            }
            if (w < 4) {
                qmx = wsum(qmx); qmn = wsum(qmn);
                if (l == 0) { sred[16+w] = qmx; sred[20+w] = qmn; }
            }
            __syncthreads();
            if (tid == 0) {
                __stcg(&d_QmaxP[bt], sred[16]+sred[17]+sred[18]+sred[19]);
                __stcg(&d_QminP[bt], sred[20]+sred[21]+sred[22]+sred[23]);
            }
        }

        grid_barrier();
    }

    // ============ finalize: t==0 blocks (one per batch) ============
    if (t == 0) {
        int bf = b;
        float s1 = 0.f;
        for (int i = tid; i < TG; i += THR) {
            int g = i % Gg, tt = i / Gg;
            float P   = __ldcg(&d_Pbuf[0][bf*TG + i]);
            float Rux = __ldcg(&d_Rup[bf*TG + i]);
            float Rdx = __ldcg(&d_Rdn[bf*TG + i]);
            float bg = bG[g];
            float C = bg * P + cG[g];
            int oi = bf*TG + g*Tt + tt;            // [b][g][t]
            out[oi] = P;
            out[BTG   + oi] = Rux;
            out[2*BTG + oi] = Rdx;
            out[3*BTG + oi] = C;
            s1 += C + 0.05f*bg*Rux + 0.02f*bg*Rdx;
        }
        float Qmax = 0.f, Qmin = 0.f;
        #pragma unroll 4
        for (int tt = 0; tt < Tt; ++tt) {
            Qmax += __ldcg(&d_QmaxP[bf*Tt + tt]);
            Qmin += __ldcg(&d_QminP[bf*Tt + tt]);
        }
        float gm = shGamma;
        float ph = 0.f;
        if (tid < Nn) {
            float Qn = 0.f;
            #pragma unroll 8
            for (int tt = 0; tt < Tt; ++tt)
                Qn += __ldcg(&d_QnP[(bf*Tt + tt)*Nn + tid]);
            float Ap = Qmax - gm * dmx;
            float Bp = Qmin - gm * dmn;
            float phi = fmaxf(Qn, fmaxf(Ap, Bp));
            out[4*BTG + bf*Nn + tid] = phi;
            ph = phi;
        }
        s1 = wsum(s1); ph = wsum(ph);
        if (l == 0) { sred[w] = s1; sred[16 + w] = ph; }
        __syncthreads();
        if (tid == 0) {
            float S = 0.f, PH = 0.f;
            #pragma unroll
            for (int i = 0; i < 16; i++) S += sred[i];
            #pragma unroll
            for (int i = 0; i < 4; i++) PH += sred[16+i];
            out[4*BTG + BN + bf]      = gm;
            out[4*BTG + BN + Bb + bf] = S + PH / (float)Nn + sEPS * gm;
        }
    }
}

extern "C" void kernel_launch(void* const* d_in, const int* in_sizes, int n_in,
                              void* d_out, int out_size) {
    const float* forecast = (const float*)d_in[0];  // [B,T]
    const float* omega    = (const float*)d_in[1];  // [B,N,T]
    const float* om_min   = (const float*)d_in[2];  // [B,T]
    const float* om_max   = (const float*)d_in[3];  // [B,T]
    const float* eps      = (const float*)d_in[4];  // [B]
    const float* pmin     = (const float*)d_in[5];  // [G]
    const float* pmax     = (const float*)d_in[6];  // [G]
    const float* bG       = (const float*)d_in[7];  // [G]
    const float* cG       = (const float*)d_in[8];  // [G]
    float* out = (float*)d_out;
    (void)in_sizes; (void)n_in; (void)out_size;

    static int attr_done = 0;
    if (!attr_done) {
        cudaFuncSetAttribute(solver, cudaFuncAttributeMaxDynamicSharedMemorySize,
                             DYN_FLOATS * (int)sizeof(float));
        attr_done = 1;
    }
    solver<<<GRID, THR, DYN_FLOATS * sizeof(float)>>>(
        forecast, omega, om_min, om_max, eps, pmin, pmax, bG, cG, out);
}

// round 14
// speedup vs baseline: 2.9905x; 1.1063x over previous
#include <cuda_runtime.h>
#include <cuda_bf16.h>

#define Bb 8
#define Nn 128
#define Gg 100
#define Tt 24
#define ITERS 40
#define LRc 2e-4f
#define TWO_RHO 20.0f
#define VOLLc 1000.0f
#define VOSPc 50.0f

#define THR  256
#define NWRP 8
#define SPW  8               // scenarios per warp (8*8 = 64 per block)
#define NSC  64              // scenarios per block

#define TG   (Tt*Gg)         // 2400
#define BTG  (Bb*TG)         // 19200
#define BN   (Bb*Nn)         // 1024
#define BT   (Bb*Tt)         // 192
#define GRID (BT*2)          // 384 blocks, 2 siblings per (b,t)
#define BPB  48              // blocks per batch (24 t * 2 siblings)

// dynamic smem layout (in floats)
#define U7_OFF  12800        // after 6400 float2 (dup,ddn interleaved)
#define U8_OFF  (U7_OFF + NWRP*104)
#define DYN_FLOATS (U8_OFF + NWRP*104)   // 14464 floats = 57856 B

// ---------------- device state (cross-block only) ----------------
__device__ float d_Pbuf[2][BTG];
__device__ float d_Rup[BTG], d_Rdn[BTG];     // written last iter only
__device__ float d_QmaxP[BT], d_QminP[BT];
__device__ float d_QnP[BT*Nn];               // [b][t][n]
__device__ float d_U7P[BT*2*Gg], d_U8P[BT*2*Gg];  // per-sibling partials

// ---------------- per-batch barrier (48 blocks each) ----------------
__device__ unsigned g_cntB[Bb*32];
__device__ volatile unsigned g_genB[Bb*32];

__device__ __forceinline__ void batch_barrier(int b) {
    __syncthreads();
    if (threadIdx.x == 0) {
        int idx = b << 5;
        __threadfence();
        unsigned gen = g_genB[idx];
        if (atomicAdd(&g_cntB[idx], 1u) == (unsigned)(BPB - 1)) {
            g_cntB[idx] = 0;
            __threadfence();
            g_genB[idx] = gen + 1u;
        } else {
            while (g_genB[idx] == gen) __nanosleep(16);
        }
        __threadfence();
    }
    __syncthreads();
}

__device__ __forceinline__ float wsum(float v) {
    #pragma unroll
    for (int o = 16; o; o >>= 1) v += __shfl_down_sync(0xffffffffu, v, o);
    return v;
}
__device__ __forceinline__ void wsum2x(float& a, float& b) {
    #pragma unroll
    for (int o = 16; o; o >>= 1) {
        a += __shfl_xor_sync(0xffffffffu, a, o);
        b += __shfl_xor_sync(0xffffffffu, b, o);
    }
}
__device__ __forceinline__ void wsum2d(float& a, float& b) {
    #pragma unroll
    for (int o = 16; o; o >>= 1) {
        a += __shfl_down_sync(0xffffffffu, a, o);
        b += __shfl_down_sync(0xffffffffu, b, o);
    }
}

// ---------------- the whole solver, one launch ----------------
__global__ __launch_bounds__(THR, 3) void solver(
    const float* __restrict__ fc,   const float* __restrict__ omega,
    const float* __restrict__ omn,  const float* __restrict__ omx,
    const float* __restrict__ eps_, const float* __restrict__ pmin_,
    const float* __restrict__ pmax_,const float* __restrict__ bG,
    const float* __restrict__ cG,   float* __restrict__ out)
{
    extern __shared__ float dyn[];
    float2* duo = (float2*)dyn;          // [64][100] (dup, ddn)
    float* u7st = dyn + U7_OFF;          // [8][104]
    float* u8st = dyn + U8_OFF;          // [8][104]

    int blk = blockIdx.x, tid = threadIdx.x;
    int w = tid >> 5, l = tid & 31;
    int nc = blk & 1;
    int bt = blk >> 1;
    int t = bt % Tt, b = bt / Tt;
    int n0 = nc * NSC;

    __shared__ float shLS[NSC], shSP[NSC], shOM[NSC], shWQ[NSC];
    __shared__ float sRu[Gg], sRd[Gg];
    __shared__ float sdux[Gg], sddx[Gg], sdui[Gg], sddi[Gg];
    __shared__ float sred[32];
    __shared__ float shQm[Tt], shQi[Tt];
    __shared__ float shc[8];
    __shared__ float shGamma, sLSx, sSPx, sLSi, sSPi;
    __shared__ float sFC, sOMN, sOMX, sEPS;

    // per-thread constants
    float bgv[4];
    #pragma unroll
    for (int j = 0; j < 4; ++j) {
        int g = l + 32*j;
        bgv[j] = (g < Gg) ? bG[g] : 0.f;
    }
    float bgs = 0.f, pmnv = 0.f, pmxv = 0.f;
    if (tid < Gg) { bgs = bG[tid]; pmnv = pmin_[tid]; pmxv = pmax_[tid]; }

    // ---- init ----
    for (int i = tid; i < NSC*Gg; i += THR) duo[i] = make_float2(0.f, 0.f);
    float dmx = 0.f, dmn = 0.f;
    if (tid < Nn) {
        #pragma unroll 4
        for (int tt = 0; tt < Tt; ++tt) {
            float om = omega[(b*Nn + tid)*Tt + tt];
            dmx += omx[b*Tt + tt] - om;
            dmn += om - omn[b*Tt + tt];
        }
    }
    if (tid < NSC) {
        shLS[tid] = 0.f; shSP[tid] = 0.f;
        shOM[tid] = omega[(b*Nn + n0 + tid)*Tt + t];
    }
    if (tid < Gg) {
        sRu[tid] = 0.f; sRd[tid] = 0.f;
        sdux[tid] = 0.f; sddx[tid] = 0.f; sdui[tid] = 0.f; sddi[tid] = 0.f;
    }
    if (tid == 0) {
        shGamma = 0.f; sLSx = 0.f; sSPx = 0.f; sLSi = 0.f; sSPi = 0.f;
        sFC = fc[bt]; sOMN = omn[bt]; sOMX = omx[bt]; sEPS = eps_[b];
    }
    __syncthreads();

    for (int it = 0; it < ITERS; ++it) {
        int pr = it & 1, pw = pr ^ 1;

        // ============ prologue: phi weights + gamma ============
        float gamma_old = shGamma;
        if (it > 0) {
            if (tid < Tt) shQm[tid] = __ldcg(&d_QmaxP[b*Tt + tid]);
            else if (tid >= 32 && tid < 32 + Tt) shQi[tid-32] = __ldcg(&d_QminP[b*Tt + tid - 32]);
        }
        __syncthreads();

        float wa = 0.f, wb = 0.f;
        if (tid < Nn) {
            float wq;
            if (it == 0) { wq = 0.5f; wa = 0.25f; wb = 0.25f; }
            else {
                float Qmax = 0.f, Qmin = 0.f;
                #pragma unroll 8
                for (int tt = 0; tt < Tt; ++tt) { Qmax += shQm[tt]; Qmin += shQi[tt]; }
                float Qn = 0.f;
                #pragma unroll 8
                for (int tt = 0; tt < Tt; ++tt)
                    Qn += __ldcg(&d_QnP[(b*Tt + tt)*Nn + tid]);
                float Ap = Qmax - gamma_old * dmx;
                float Bp = Qmin - gamma_old * dmn;
                float M  = fmaxf(Ap, Bp);
                wq = (Qn > M) ? 1.f : ((Qn == M) ? 0.5f : 0.f);
                float aw = (Ap > Bp) ? 1.f : ((Ap == Bp) ? 0.5f : 0.f);
                float bw = (Bp > Ap) ? 1.f : ((Ap == Bp) ? 0.5f : 0.f);
                float wm = 1.f - wq;
                wa = wm * aw; wb = wm * bw;
            }
            if (tid >= n0 && tid < n0 + NSC)
                shWQ[tid - n0] = wq * (1.f / (float)Nn);
        }
        if (w < 4) {
            float v0 = wsum(wa), v1 = wsum(wb), v2 = wsum(wa * dmx), v3 = wsum(wb * dmn);
            if (l == 0) { sred[w] = v0; sred[4+w] = v1; sred[8+w] = v2; sred[12+w] = v3; }
        }
        __syncthreads();
        if (tid == 0) {
            float A = sred[0]+sred[1]+sred[2]+sred[3];
            float B = sred[4]+sred[5]+sred[6]+sred[7];
            float C = sred[8]+sred[9]+sred[10]+sred[11];
            float D = sred[12]+sred[13]+sred[14]+sred[15];
            float inv = 1.f / (float)Nn;
            shc[3] = A*inv; shc[4] = B*inv;
            shGamma = fmaxf(gamma_old - LRc * (sEPS - C*inv - D*inv), 0.f);
        }
        __syncthreads();

        // ============ big phase: warp w -> local scenarios w*8..w*8+7 ======
        float u7a[4] = {0,0,0,0}, u8a[4] = {0,0,0,0};
        #pragma unroll
        for (int sp = 0; sp < SPW/2; ++sp) {
            int si0 = w*SPW + 2*sp, si1 = si0 + 1;
            int r0 = si0*Gg, r1 = si1*Gg;
            float du0[4], dd0[4], du1[4], dd1[4];
            #pragma unroll
            for (int j = 0; j < 4; ++j) {
                int g = l + 32*j;
                if (g < Gg) {
                    float2 v0 = duo[r0 + g]; du0[j] = v0.x; dd0[j] = v0.y;
                    float2 v1 = duo[r1 + g]; du1[j] = v1.x; dd1[j] = v1.y;
                } else { du0[j]=dd0[j]=du1[j]=dd1[j]=0.f; }
            }
            float r20 = (du0[0]-dd0[0]) + (du0[1]-dd0[1]) + (du0[2]-dd0[2]) + (du0[3]-dd0[3]);
            float r21 = (du1[0]-dd1[0]) + (du1[1]-dd1[1]) + (du1[2]-dd1[2]) + (du1[3]-dd1[3]);
            wsum2x(r20, r21);
            r20 += shLS[si0] - shSP[si0] - shOM[si0];
            r21 += shLS[si1] - shSP[si1] - shOM[si1];
            float wq0 = shWQ[si0], wq1 = shWQ[si1];
            float q0 = 0.f, q1 = 0.f;
            #pragma unroll
            for (int j = 0; j < 4; ++j) {
                int g = l + 32*j;
                if (g < Gg) {
                    float rtu = 2.0f * bgv[j], rtd = 0.5f * bgv[j];
                    float Ruj = sRu[g], Rdj = sRd[g];
                    float rl7 = fmaxf(du0[j] - Ruj, 0.f);
                    float rl8 = fmaxf(dd0[j] - Rdj, 0.f);
                    u7a[j] += rl7; u8a[j] += rl8;
                    float ndu = fmaxf(du0[j] - LRc * (wq0*rtu + TWO_RHO * (r20 + rl7)), 0.f);
                    float ndd = fmaxf(dd0[j] - LRc * (wq0*rtd + TWO_RHO * (rl8 - r20)), 0.f);
                    duo[r0 + g] = make_float2(ndu, ndd);
                    q0 += rtu*ndu + rtd*ndd;
                    rl7 = fmaxf(du1[j] - Ruj, 0.f);
                    rl8 = fmaxf(dd1[j] - Rdj, 0.f);
                    u7a[j] += rl7; u8a[j] += rl8;
                    ndu = fmaxf(du1[j] - LRc * (wq1*rtu + TWO_RHO * (r21 + rl7)), 0.f);
                    ndd = fmaxf(dd1[j] - LRc * (wq1*rtd + TWO_RHO * (rl8 - r21)), 0.f);
                    duo[r1 + g] = make_float2(ndu, ndd);
                    q1 += rtu*ndu + rtd*ndd;
                }
            }
            float qls0 = 0.f, qls1 = 0.f;
            if (l == 0) {
                float lsn = fmaxf(shLS[si0] - LRc * (wq0*VOLLc + TWO_RHO*r20), 0.f);
                float spn = fmaxf(shSP[si0] - LRc * (wq0*VOSPc - TWO_RHO*r20), 0.f);
                shLS[si0] = lsn; shSP[si0] = spn;
                qls0 = VOLLc*lsn + VOSPc*spn;
                lsn = fmaxf(shLS[si1] - LRc * (wq1*VOLLc + TWO_RHO*r21), 0.f);
                spn = fmaxf(shSP[si1] - LRc * (wq1*VOSPc - TWO_RHO*r21), 0.f);
                shLS[si1] = lsn; shSP[si1] = spn;
                qls1 = VOLLc*lsn + VOSPc*spn;
            }
            wsum2d(q0, q1);
            if (l == 0) {
                __stcg(&d_QnP[bt*Nn + n0 + si0], q0 + qls0);
                __stcg(&d_QnP[bt*Nn + n0 + si1], q1 + qls1);
            }
        }
        // stage per-warp U7/U8, reduce, publish sibling partial
        #pragma unroll
        for (int j = 0; j < 4; ++j) {
            int g = l + 32*j;
            if (g < Gg) { u7st[w*104 + g] = u7a[j]; u8st[w*104 + g] = u8a[j]; }
        }
        __syncthreads();
        if (tid < 200) {
            int g = (tid < 100) ? tid : tid - 100;
            float* src = (tid < 100) ? u7st : u8st;
            float s = 0.f;
            #pragma unroll
            for (int ww = 0; ww < NWRP; ++ww) s += src[ww*104 + g];
            if (tid < 100) __stcg(&d_U7P[(bt*2 + nc)*Gg + g], s);
            else           __stcg(&d_U8P[(bt*2 + nc)*Gg + g], s);
        }

        batch_barrier(b);    // BAR_A: U7 partials visible to sibling

        // ============ small phase (duplicated in both siblings) ============
        {
            int g = tid;
            bool act = (g < Gg);
            int idx = bt*Gg + g;
            float P=0,Pm=0,Pp=0,Rux=0,Rdx=0,dux=0,ddx=0,dui=0,ddi=0,U7=0,U8=0;
            if (act) {
                if (it == 0) { float pv = 0.5f*(pmnv + pmxv); P = pv; Pm = pv; Pp = pv; }
                else {
                    P = __ldcg(&d_Pbuf[pr][idx]);
                    if (t > 0)      Pm = __ldcg(&d_Pbuf[pr][idx - Gg]);
                    if (t < Tt - 1) Pp = __ldcg(&d_Pbuf[pr][idx + Gg]);
                }
                Rux = sRu[g]; Rdx = sRd[g];
                dux = sdux[g]; ddx = sddx[g]; dui = sdui[g]; ddi = sddi[g];
                U7 = __ldcg(&d_U7P[bt*2*Gg + g]) + __ldcg(&d_U7P[(bt*2+1)*Gg + g]);
                U8 = __ldcg(&d_U8P[bt*2*Gg + g]) + __ldcg(&d_U8P[(bt*2+1)*Gg + g]);
            }
            float s1 = 0.f, s3 = 0.f, s4 = 0.f;
            if (act) { s1 = P; s3 = dux - ddx; s4 = dui - ddi; }
            if (w < 4) {
                s1 = wsum(s1); s3 = wsum(s3); s4 = wsum(s4);
                if (l == 0) { sred[16+w] = s1; sred[20+w] = s3; sred[24+w] = s4; }
            }
            __syncthreads();
            if (tid == 0) {
                shc[0] = sred[16]+sred[17]+sred[18]+sred[19] - sFC;
                shc[1] = sred[20]+sred[21]+sred[22]+sred[23] + sLSx - sSPx - sOMX;
                shc[2] = sred[24]+sred[25]+sred[26]+sred[27] + sLSi - sSPi - sOMN;
            }
            __syncthreads();
            float r1 = shc[0], r3 = shc[1], r4 = shc[2], WA = shc[3], WB = shc[4];
            float qmx = 0.f, qmn = 0.f;
            if (act) {
                float rtu = 2.f*bgs, rtd = 0.5f*bgs;
                float r5  = fmaxf(P + Rux - pmxv, 0.f);
                float r6  = fmaxf(pmnv - P + Rdx, 0.f);
                float r9  = fmaxf(dux - Rux, 0.f), r10 = fmaxf(ddx - Rdx, 0.f);
                float r11 = fmaxf(dui - Rux, 0.f), r12 = fmaxf(ddi - Rdx, 0.f);
                float sl = 0.f, sr = 0.f;
                if (t > 0)      { float dp = P - Pm; float rl = fmaxf(fabsf(dp) - pmxv, 0.f); sl = (dp > 0.f) ? rl : -rl; }
                if (t < Tt - 1) { float dp = Pp - P; float rl = fmaxf(fabsf(dp) - pmxv, 0.f); sr = (dp > 0.f) ? rl : -rl; }
                float nP = P - LRc * (bgs + TWO_RHO * (r1 + r5 - r6 + sl - sr));
                nP = fminf(fmaxf(nP, pmnv), pmxv);
                float nRu = fmaxf(Rux - LRc * (0.05f*bgs + TWO_RHO * (r5 - U7 - r9 - r11)), 0.f);
                float nRd = fmaxf(Rdx - LRc * (0.02f*bgs + TWO_RHO * (r6 - U8 - r10 - r12)), 0.f);
                float ndux = fmaxf(dux - LRc * (WA*rtu + TWO_RHO * ( r3 + r9 )), 0.f);
                float nddx = fmaxf(ddx - LRc * (WA*rtd + TWO_RHO * (-r3 + r10)), 0.f);
                float ndui = fmaxf(dui - LRc * (WB*rtu + TWO_RHO * ( r4 + r11)), 0.f);
                float nddi = fmaxf(ddi - LRc * (WB*rtd + TWO_RHO * (-r4 + r12)), 0.f);
                __stcg(&d_Pbuf[pw][idx], nP);
                sRu[g] = nRu; sRd[g] = nRd;
                sdux[g] = ndux; sddx[g] = nddx; sdui[g] = ndui; sddi[g] = nddi;
                if (it == ITERS - 1) { __stcg(&d_Rup[idx], nRu); __stcg(&d_Rdn[idx], nRd); }
                qmx = rtu*ndux + rtd*nddx;
                qmn = rtu*ndui + rtd*nddi;
            }
            if (tid == 0) {
                float v;
                v = fmaxf(sLSx - LRc*(WA*VOLLc + TWO_RHO*r3), 0.f); sLSx = v; qmx += VOLLc*v;
                v = fmaxf(sSPx - LRc*(WA*VOSPc - TWO_RHO*r3), 0.f); sSPx = v; qmx += VOSPc*v;
                v = fmaxf(sLSi - LRc*(WB*VOLLc + TWO_RHO*r4), 0.f); sLSi = v; qmn += VOLLc*v;
                v = fmaxf(sSPi - LRc*(WB*VOSPc - TWO_RHO*r4), 0.f); sSPi = v; qmn += VOSPc*v;
            }
            if (w < 4) {
                qmx = wsum(qmx); qmn = wsum(qmn);
                if (l == 0) { sred[16+w] = qmx; sred[20+w] = qmn; }
            }
            __syncthreads();
            if (tid == 0) {
                __stcg(&d_QmaxP[bt], sred[16]+sred[17]+sred[18]+sred[19]);
                __stcg(&d_QminP[bt], sred[20]+sred[21]+sred[22]+sred[23]);
            }
        }

        batch_barrier(b);    // BAR_B: QmaxP/Pbuf visible for next prologue/small
    }

    // ============ finalize: (t==0, nc==0) blocks, one per batch ============
    if (t == 0 && nc == 0) {
        int bf = b;
        float s1 = 0.f;
        for (int i = tid; i < TG; i += THR) {
            int g = i % Gg, tt = i / Gg;
            float P   = __ldcg(&d_Pbuf[0][bf*TG + i]);
            float Rux = __ldcg(&d_Rup[bf*TG + i]);
            float Rdx = __ldcg(&d_Rdn[bf*TG + i]);
            float bg = bG[g];
            float C = bg * P + cG[g];
            int oi = bf*TG + g*Tt + tt;            // [b][g][t]
            out[oi] = P;
            out[BTG   + oi] = Rux;
            out[2*BTG + oi] = Rdx;
            out[3*BTG + oi] = C;
            s1 += C + 0.05f*bg*Rux + 0.02f*bg*Rdx;
        }
        float Qmax = 0.f, Qmin = 0.f;
        #pragma unroll 4
        for (int tt = 0; tt < Tt; ++tt) {
            Qmax += __ldcg(&d_QmaxP[bf*Tt + tt]);
            Qmin += __ldcg(&d_QminP[bf*Tt + tt]);
        }
        float gm = shGamma;
        float ph = 0.f;
        if (tid < Nn) {
            float Qn = 0.f;
            #pragma unroll 8
            for (int tt = 0; tt < Tt; ++tt)
                Qn += __ldcg(&d_QnP[(bf*Tt + tt)*Nn + tid]);
            float Ap = Qmax - gm * dmx;
            float Bp = Qmin - gm * dmn;
            float phi = fmaxf(Qn, fmaxf(Ap, Bp));
            out[4*BTG + bf*Nn + tid] = phi;
            ph = phi;
        }
        s1 = wsum(s1); ph = wsum(ph);
        if (l == 0) { sred[w] = s1; sred[16 + w] = ph; }
        __syncthreads();
        if (tid == 0) {
            float S = 0.f, PH = 0.f;
            #pragma unroll
            for (int i = 0; i < NWRP; i++) S += sred[i];
            #pragma unroll
            for (int i = 0; i < 4; i++) PH += sred[16+i];
            out[4*BTG + BN + bf]      = gm;
            out[4*BTG + BN + Bb + bf] = S + PH / (float)Nn + sEPS * gm;
        }
    }
}

extern "C" void kernel_launch(void* const* d_in, const int* in_sizes, int n_in,
                              void* d_out, int out_size) {
    const float* forecast = (const float*)d_in[0];  // [B,T]
    const float* omega    = (const float*)d_in[1];  // [B,N,T]
    const float* om_min   = (const float*)d_in[2];  // [B,T]
    const float* om_max   = (const float*)d_in[3];  // [B,T]
    const float* eps      = (const float*)d_in[4];  // [B]
    const float* pmin     = (const float*)d_in[5];  // [G]
    const float* pmax     = (const float*)d_in[6];  // [G]
    const float* bG       = (const float*)d_in[7];  // [G]
    const float* cG       = (const float*)d_in[8];  // [G]
    float* out = (float*)d_out;
    (void)in_sizes; (void)n_in; (void)out_size;

    static int attr_done = 0;
    if (!attr_done) {
        cudaFuncSetAttribute(solver, cudaFuncAttributeMaxDynamicSharedMemorySize,
                             DYN_FLOATS * (int)sizeof(float));
        attr_done = 1;
    }
    solver<<<GRID, THR, DYN_FLOATS * sizeof(float)>>>(
        forecast, omega, om_min, om_max, eps, pmin, pmax, bG, cG, out);
}